// round 1
// baseline (speedup 1.0000x reference)
#include <cuda_runtime.h>
#include <math.h>

#define NS 100000
#define D  128
#define H  512
#define KK 343

// Scratch (device globals; no allocation allowed)
__device__ float g_xn[(size_t)NS * D];      // LN output, 51.2 MB
__device__ float g_h [(size_t)NS * H];      // GELU output, 204.8 MB
__device__ float g_gsum[H];
__device__ float g_scale[H];

// ---------------------------------------------------------------------------
// K1: sparse depthwise conv (compacted over valid neighbors) + LayerNorm
// 1 block per site, 128 threads = 1 channel each.
// ---------------------------------------------------------------------------
__global__ __launch_bounds__(128) void k1_dwln(
    const float* __restrict__ feats, const int* __restrict__ nidx,
    const float* __restrict__ dww,   const float* __restrict__ dwb,
    const float* __restrict__ lng,   const float* __restrict__ lnb)
{
    const int site = blockIdx.x;
    const int tid  = threadIdx.x;
    const int lane = tid & 31, warp = tid >> 5;

    // block 0 also zeroes the global sq-sum accumulator (K2 runs strictly after K1)
    if (blockIdx.x == 0) {
        for (int j = tid; j < H; j += 128) g_gsum[j] = 0.f;
    }

    __shared__ int   s_kid[KK];
    __shared__ int   s_wbase[4];
    __shared__ int   s_total;
    __shared__ float s_ws[4], s_ws2[4];

    const int* row = nidx + (size_t)site * KK;

    // Each thread owns k = tid, tid+128, tid+256 (deterministic order)
    const int k0 = tid, k1 = tid + 128, k2 = tid + 256;
    int id0 = row[k0];
    int id1 = row[k1];
    int id2 = (k2 < KK) ? row[k2] : NS;
    int v0 = (id0 != NS), v1 = (id1 != NS), v2 = (id2 != NS);
    int cnt = v0 + v1 + v2;

    // warp inclusive scan of cnt
    int incl = cnt;
    #pragma unroll
    for (int o = 1; o < 32; o <<= 1) {
        int v = __shfl_up_sync(0xffffffffu, incl, o);
        if (lane >= o) incl += v;
    }
    if (lane == 31) s_wbase[warp] = incl;
    __syncthreads();
    if (tid == 0) {
        int t0 = s_wbase[0], t1 = s_wbase[1], t2 = s_wbase[2], t3 = s_wbase[3];
        s_wbase[0] = 0; s_wbase[1] = t0; s_wbase[2] = t0 + t1; s_wbase[3] = t0 + t1 + t2;
        s_total = t0 + t1 + t2 + t3;
    }
    __syncthreads();
    int off = s_wbase[warp] + incl - cnt;
    if (v0) s_kid[off++] = (k0 << 17) | id0;
    if (v1) s_kid[off++] = (k1 << 17) | id1;
    if (v2) s_kid[off  ] = (k2 << 17) | id2;
    __syncthreads();

    const int nv = s_total;
    float acc = 0.f;
    for (int j = 0; j < nv; j++) {
        int kid = s_kid[j];                  // uniform across block
        int id  = kid & 0x1ffff;
        int k   = kid >> 17;
        acc += feats[id * D + tid] * dww[k * D + tid];
    }
    float x = acc + dwb[tid];

    // LayerNorm over 128 channels (one value per thread)
    float s = x, s2 = x * x;
    #pragma unroll
    for (int o = 16; o > 0; o >>= 1) {
        s  += __shfl_xor_sync(0xffffffffu, s,  o);
        s2 += __shfl_xor_sync(0xffffffffu, s2, o);
    }
    if (lane == 0) { s_ws[warp] = s; s_ws2[warp] = s2; }
    __syncthreads();
    s  = s_ws[0]  + s_ws[1]  + s_ws[2]  + s_ws[3];
    s2 = s_ws2[0] + s_ws2[1] + s_ws2[2] + s_ws2[3];
    float mu  = s  * (1.f / 128.f);
    float var = s2 * (1.f / 128.f) - mu * mu;
    float inv = rsqrtf(var + 1e-6f);
    g_xn[site * D + tid] = (x - mu) * inv * lng[tid] + lnb[tid];
}

// ---------------------------------------------------------------------------
// K2: GEMM1  h = gelu(xn @ w1 + b1), + per-channel partial sum of h^2
// BM=64, BN=64, K=128 (two BK=64 chunks), 256 threads, 4x4 micro-tile
// ---------------------------------------------------------------------------
__global__ __launch_bounds__(256) void k2_gemm1(
    const float* __restrict__ w1, const float* __restrict__ b1)
{
    __shared__ float As[64][68];   // padded: conflict-free broadcast reads
    __shared__ float Bs[64][64];
    __shared__ float red[16][64];

    const int m0 = blockIdx.x * 64;
    const int n0 = blockIdx.y * 64;
    const int tid = threadIdx.x;
    const int tr = tid >> 4, tc = tid & 15;
    const int r0 = tr * 4,  c0 = tc * 4;

    float acc[4][4] = {};

    for (int k0 = 0; k0 < 128; k0 += 64) {
        #pragma unroll
        for (int j = 0; j < 4; j++) {
            int t = tid + j * 256;
            int r = t >> 4, q = t & 15;
            int gr = m0 + r;
            float4 v = make_float4(0.f, 0.f, 0.f, 0.f);
            if (gr < NS) v = *(const float4*)(g_xn + (size_t)gr * 128 + k0 + q * 4);
            *(float4*)&As[r][q * 4] = v;
        }
        #pragma unroll
        for (int j = 0; j < 4; j++) {
            int t = tid + j * 256;
            int kk = t >> 4, q = t & 15;
            *(float4*)&Bs[kk][q * 4] =
                *(const float4*)(w1 + (size_t)(k0 + kk) * 512 + n0 + q * 4);
        }
        __syncthreads();
        #pragma unroll
        for (int k = 0; k < 64; k++) {
            float4 b = *(float4*)&Bs[k][c0];
            float a[4];
            #pragma unroll
            for (int i = 0; i < 4; i++) a[i] = As[r0 + i][k];
            #pragma unroll
            for (int i = 0; i < 4; i++) {
                acc[i][0] += a[i] * b.x;
                acc[i][1] += a[i] * b.y;
                acc[i][2] += a[i] * b.z;
                acc[i][3] += a[i] * b.w;
            }
        }
        __syncthreads();
    }

    // epilogue: bias + exact GELU, store h, partial sum of squares
    float p[4] = {0.f, 0.f, 0.f, 0.f};
    #pragma unroll
    for (int i = 0; i < 4; i++) {
        int gr = m0 + r0 + i;
        #pragma unroll
        for (int j = 0; j < 4; j++) {
            int gn = n0 + c0 + j;
            float v = acc[i][j] + b1[gn];
            float g = 0.5f * v * (1.f + erff(v * 0.70710678118654752f));
            if (gr < NS) {
                g_h[(size_t)gr * 512 + gn] = g;
                p[j] += g * g;
            }
        }
    }
    #pragma unroll
    for (int j = 0; j < 4; j++) red[tr][c0 + j] = p[j];
    __syncthreads();
    if (tid < 64) {
        float s = 0.f;
        #pragma unroll
        for (int t = 0; t < 16; t++) s += red[t][tid];
        atomicAdd(&g_gsum[n0 + tid], s);
    }
}

// ---------------------------------------------------------------------------
// K3: GRN scale: gx = sqrt(gsum); nx = gx/(mean(gx)+eps); scale = grn_g*nx + 1
// ---------------------------------------------------------------------------
__global__ void k3_grn(const float* __restrict__ grng)
{
    const int c = threadIdx.x;       // 512 threads
    const int lane = c & 31, warp = c >> 5;
    float gx = sqrtf(g_gsum[c]);

    __shared__ float ws[16];
    __shared__ float s_tot;
    float s = gx;
    #pragma unroll
    for (int o = 16; o > 0; o >>= 1) s += __shfl_xor_sync(0xffffffffu, s, o);
    if (lane == 0) ws[warp] = s;
    __syncthreads();
    if (c == 0) {
        float t = 0.f;
        #pragma unroll
        for (int i = 0; i < 16; i++) t += ws[i];
        s_tot = t;
    }
    __syncthreads();
    float mean = s_tot * (1.f / 512.f);
    g_scale[c] = grng[c] * (gx / (mean + 1e-6f)) + 1.f;
}

// ---------------------------------------------------------------------------
// K4: GEMM2 with fused GRN transform on A-load:
//   out = ((h*scale + grn_b) @ w2) + b2 + feats
// BM=64, BN=128, BK=32 (16 chunks), 256 threads, 8x4 micro-tile
// ---------------------------------------------------------------------------
__global__ __launch_bounds__(256) void k4_gemm2(
    const float* __restrict__ w2,   const float* __restrict__ b2,
    const float* __restrict__ grnb, const float* __restrict__ feats,
    float* __restrict__ out)
{
    __shared__ float As[64][32];
    __shared__ float Bs[32][128];

    const int m0 = blockIdx.x * 64;
    const int tid = threadIdx.x;
    const int tr = tid >> 5, tc = tid & 31;
    const int r0 = tr * 8,  c0 = tc * 4;

    float acc[8][4] = {};

    for (int k0 = 0; k0 < 512; k0 += 32) {
        #pragma unroll
        for (int j = 0; j < 2; j++) {
            int t = tid + j * 256;           // 512 float4 total
            int r = t >> 3, q = t & 7;
            int gr = m0 + r;
            float4 v = make_float4(0.f, 0.f, 0.f, 0.f);
            if (gr < NS) {
                float4 hv = *(const float4*)(g_h + (size_t)gr * 512 + k0 + q * 4);
                float4 sc = *(const float4*)(g_scale + k0 + q * 4);
                float4 gb = *(const float4*)(grnb + k0 + q * 4);
                v.x = hv.x * sc.x + gb.x;
                v.y = hv.y * sc.y + gb.y;
                v.z = hv.z * sc.z + gb.z;
                v.w = hv.w * sc.w + gb.w;
            }
            *(float4*)&As[r][q * 4] = v;
        }
        #pragma unroll
        for (int j = 0; j < 4; j++) {
            int t = tid + j * 256;           // 1024 float4 total
            int kk = t >> 5, q = t & 31;
            *(float4*)&Bs[kk][q * 4] =
                *(const float4*)(w2 + (size_t)(k0 + kk) * 128 + q * 4);
        }
        __syncthreads();
        #pragma unroll
        for (int k = 0; k < 32; k++) {
            float4 b = *(float4*)&Bs[k][c0];
            #pragma unroll
            for (int i = 0; i < 8; i++) {
                float a = As[r0 + i][k];     // warp-uniform row -> broadcast
                acc[i][0] += a * b.x;
                acc[i][1] += a * b.y;
                acc[i][2] += a * b.z;
                acc[i][3] += a * b.w;
            }
        }
        __syncthreads();
    }

    #pragma unroll
    for (int i = 0; i < 8; i++) {
        int gr = m0 + r0 + i;
        if (gr < NS) {
            #pragma unroll
            for (int j = 0; j < 4; j++) {
                int gn = c0 + j;
                out[(size_t)gr * 128 + gn] = acc[i][j] + b2[gn]
                                           + feats[(size_t)gr * 128 + gn];
            }
        }
    }
}

// ---------------------------------------------------------------------------
extern "C" void kernel_launch(void* const* d_in, const int* in_sizes, int n_in,
                              void* d_out, int out_size)
{
    const float* feats = (const float*)d_in[0];
    const int*   nidx  = (const int*)  d_in[1];
    const float* dww   = (const float*)d_in[2];
    const float* dwb   = (const float*)d_in[3];
    const float* lng   = (const float*)d_in[4];
    const float* lnb   = (const float*)d_in[5];
    const float* w1    = (const float*)d_in[6];
    const float* b1    = (const float*)d_in[7];
    const float* grng  = (const float*)d_in[8];
    const float* grnb  = (const float*)d_in[9];
    const float* w2    = (const float*)d_in[10];
    const float* b2    = (const float*)d_in[11];
    float* out = (float*)d_out;

    k1_dwln<<<NS, 128>>>(feats, nidx, dww, dwb, lng, lnb);

    dim3 g2((NS + 63) / 64, H / 64);
    k2_gemm1<<<g2, 256>>>(w1, b1);

    k3_grn<<<1, H>>>(grng);

    k4_gemm2<<<(NS + 63) / 64, 256>>>(w2, b2, grnb, feats, out);
}

// round 3
// speedup vs baseline: 2.0431x; 2.0431x over previous
#include <cuda_runtime.h>
#include <math.h>

#define NS 100000
#define D  128
#define H  512
#define KK 343

// Scratch (device globals; no allocation allowed)
__device__ float g_xn[(size_t)NS * D];      // LN output, 51.2 MB
__device__ float g_h [(size_t)NS * H];      // GELU output, 204.8 MB
__device__ float g_gsum[H];
__device__ float g_scale[H];

__device__ __forceinline__ unsigned f2tf32(float x) {
    unsigned r;
    asm("cvt.rna.tf32.f32 %0, %1;" : "=r"(r) : "f"(x));
    return r;
}

__device__ __forceinline__ void mma_tf32(float* c, const unsigned* a, const unsigned* b) {
    asm volatile(
        "mma.sync.aligned.m16n8k8.row.col.f32.tf32.tf32.f32 "
        "{%0,%1,%2,%3}, {%4,%5,%6,%7}, {%8,%9}, {%0,%1,%2,%3};"
        : "+f"(c[0]), "+f"(c[1]), "+f"(c[2]), "+f"(c[3])
        : "r"(a[0]), "r"(a[1]), "r"(a[2]), "r"(a[3]), "r"(b[0]), "r"(b[1]));
}

// ---------------------------------------------------------------------------
// K1: sparse depthwise conv + LayerNorm. One WARP per site, float4 per lane.
// ---------------------------------------------------------------------------
__global__ __launch_bounds__(256) void k1_dwln(
    const float* __restrict__ feats, const int* __restrict__ nidx,
    const float* __restrict__ dww,   const float* __restrict__ dwb,
    const float* __restrict__ lng,   const float* __restrict__ lnb)
{
    const int tid  = threadIdx.x;
    const int lane = tid & 31, warp = tid >> 5;
    const int site = blockIdx.x * 8 + warp;

    // block 0 zeroes the global sq-sum accumulator (K2 runs strictly after K1)
    if (blockIdx.x == 0) {
        if (tid < H) g_gsum[tid] = 0.f;
        if (tid + 256 < H) g_gsum[tid + 256] = 0.f;
    }

    __shared__ int s_list[8][KK];

    const int* row = nidx + (size_t)site * KK;
    int cnt = 0;
    #pragma unroll
    for (int base = 0; base < KK; base += 32) {
        int k  = base + lane;
        int id = (k < KK) ? row[k] : NS;
        bool v = (id != NS);
        unsigned m = __ballot_sync(0xffffffffu, v);
        if (v) s_list[warp][cnt + __popc(m & ((1u << lane) - 1u))] = (k << 17) | id;
        cnt += __popc(m);
    }
    __syncwarp();

    const int c4 = lane * 4;
    float4 acc = make_float4(0.f, 0.f, 0.f, 0.f);
    for (int j = 0; j < cnt; j++) {
        int kid = s_list[warp][j];            // warp-uniform
        int id  = kid & 0x1ffff;
        int k   = kid >> 17;
        float4 f = *(const float4*)(feats + (size_t)id * D + c4);
        float4 w = *(const float4*)(dww   + (size_t)k  * D + c4);
        acc.x += f.x * w.x; acc.y += f.y * w.y;
        acc.z += f.z * w.z; acc.w += f.w * w.w;
    }
    float4 bb = *(const float4*)(dwb + c4);
    float4 x = make_float4(acc.x + bb.x, acc.y + bb.y, acc.z + bb.z, acc.w + bb.w);

    float s  = x.x + x.y + x.z + x.w;
    float s2 = x.x * x.x + x.y * x.y + x.z * x.z + x.w * x.w;
    #pragma unroll
    for (int o = 16; o > 0; o >>= 1) {
        s  += __shfl_xor_sync(0xffffffffu, s,  o);
        s2 += __shfl_xor_sync(0xffffffffu, s2, o);
    }
    float mu  = s  * (1.f / 128.f);
    float var = s2 * (1.f / 128.f) - mu * mu;
    float inv = rsqrtf(var + 1e-6f);

    float4 gg = *(const float4*)(lng + c4);
    float4 be = *(const float4*)(lnb + c4);
    float4 o;
    o.x = (x.x - mu) * inv * gg.x + be.x;
    o.y = (x.y - mu) * inv * gg.y + be.y;
    o.z = (x.z - mu) * inv * gg.z + be.z;
    o.w = (x.w - mu) * inv * gg.w + be.w;
    *(float4*)(g_xn + (size_t)site * D + c4) = o;
}

// ---------------------------------------------------------------------------
// K2: GEMM1 (tf32 mma): h = gelu(xn @ w1 + b1), + per-channel sum of h^2
// BM=128, BN=128, BK=32; 8 warps (4x2), warp tile 32x64 (2 m16 x 8 n8)
// ---------------------------------------------------------------------------
__global__ __launch_bounds__(256) void k2_gemm1(
    const float* __restrict__ w1, const float* __restrict__ b1)
{
    __shared__ unsigned As[128][36];
    __shared__ unsigned Bs[32][136];
    __shared__ float s_gsum[128];

    const int tid = threadIdx.x;
    const int m0 = blockIdx.x * 128;
    const int n0 = blockIdx.y * 128;
    const int lane = tid & 31, warpId = tid >> 5;
    const int wr = warpId & 3, wc = warpId >> 2;
    const int g = lane >> 2, tig = lane & 3;

    if (tid < 128) s_gsum[tid] = 0.f;

    float acc[2][8][4] = {};

    for (int k0 = 0; k0 < 128; k0 += 32) {
        #pragma unroll
        for (int j = 0; j < 4; j++) {
            int idx = tid + j * 256;
            int r = idx >> 3, q = idx & 7;
            int gr = m0 + r;
            float4 v = make_float4(0.f, 0.f, 0.f, 0.f);
            if (gr < NS) v = *(const float4*)(g_xn + (size_t)gr * 128 + k0 + q * 4);
            *(uint4*)&As[r][q * 4] =
                make_uint4(f2tf32(v.x), f2tf32(v.y), f2tf32(v.z), f2tf32(v.w));
        }
        #pragma unroll
        for (int j = 0; j < 4; j++) {
            int idx = tid + j * 256;
            int kk = idx >> 5, q = idx & 31;
            float4 v = *(const float4*)(w1 + (size_t)(k0 + kk) * 512 + n0 + q * 4);
            *(uint4*)&Bs[kk][q * 4] =
                make_uint4(f2tf32(v.x), f2tf32(v.y), f2tf32(v.z), f2tf32(v.w));
        }
        __syncthreads();

        #pragma unroll
        for (int ks = 0; ks < 32; ks += 8) {
            unsigned bfr[8][2];
            #pragma unroll
            for (int j = 0; j < 8; j++) {
                int col = wc * 64 + j * 8 + g;
                bfr[j][0] = Bs[ks + tig][col];
                bfr[j][1] = Bs[ks + tig + 4][col];
            }
            #pragma unroll
            for (int i = 0; i < 2; i++) {
                int rb = wr * 32 + i * 16 + g;
                unsigned afr[4];
                afr[0] = As[rb][ks + tig];
                afr[1] = As[rb + 8][ks + tig];
                afr[2] = As[rb][ks + tig + 4];
                afr[3] = As[rb + 8][ks + tig + 4];
                #pragma unroll
                for (int j = 0; j < 8; j++) mma_tf32(acc[i][j], afr, bfr[j]);
            }
        }
        __syncthreads();
    }

    // epilogue: bias + exact GELU, store h, square-sum reduce
    float p[8][2] = {};
    #pragma unroll
    for (int i = 0; i < 2; i++) {
        int r0r = m0 + wr * 32 + i * 16 + g;
        #pragma unroll
        for (int j = 0; j < 8; j++) {
            int cc = n0 + wc * 64 + j * 8 + 2 * tig;
            float b0v = b1[cc], b1v = b1[cc + 1];
            #pragma unroll
            for (int h = 0; h < 2; h++) {           // h=0: row r0r, h=1: row r0r+8
                int rr = r0r + h * 8;
                if (rr < NS) {
                    float v0 = acc[i][j][2 * h + 0] + b0v;
                    float v1 = acc[i][j][2 * h + 1] + b1v;
                    float g0 = 0.5f * v0 * (1.f + erff(v0 * 0.70710678118654752f));
                    float g1 = 0.5f * v1 * (1.f + erff(v1 * 0.70710678118654752f));
                    g_h[(size_t)rr * 512 + cc]     = g0;
                    g_h[(size_t)rr * 512 + cc + 1] = g1;
                    p[j][0] += g0 * g0;
                    p[j][1] += g1 * g1;
                }
            }
        }
    }
    // reduce across lanes with the same tig (sum over g)
    #pragma unroll
    for (int j = 0; j < 8; j++) {
        #pragma unroll
        for (int c = 0; c < 2; c++) {
            #pragma unroll
            for (int o = 4; o < 32; o <<= 1)
                p[j][c] += __shfl_xor_sync(0xffffffffu, p[j][c], o);
        }
    }
    if (lane < 4) {
        #pragma unroll
        for (int j = 0; j < 8; j++) {
            atomicAdd(&s_gsum[wc * 64 + j * 8 + 2 * lane],     p[j][0]);
            atomicAdd(&s_gsum[wc * 64 + j * 8 + 2 * lane + 1], p[j][1]);
        }
    }
    __syncthreads();
    if (tid < 128) atomicAdd(&g_gsum[n0 + tid], s_gsum[tid]);
}

// ---------------------------------------------------------------------------
// K3: GRN scale: gx = sqrt(gsum); nx = gx/(mean(gx)+eps); scale = grn_g*nx + 1
// ---------------------------------------------------------------------------
__global__ void k3_grn(const float* __restrict__ grng)
{
    const int c = threadIdx.x;       // 512 threads
    const int lane = c & 31, warp = c >> 5;
    float gx = sqrtf(g_gsum[c]);

    __shared__ float ws[16];
    __shared__ float s_tot;
    float s = gx;
    #pragma unroll
    for (int o = 16; o > 0; o >>= 1) s += __shfl_xor_sync(0xffffffffu, s, o);
    if (lane == 0) ws[warp] = s;
    __syncthreads();
    if (c == 0) {
        float t = 0.f;
        #pragma unroll
        for (int i = 0; i < 16; i++) t += ws[i];
        s_tot = t;
    }
    __syncthreads();
    float mean = s_tot * (1.f / 512.f);
    g_scale[c] = grng[c] * (gx / (mean + 1e-6f)) + 1.f;
}

// ---------------------------------------------------------------------------
// K4: GEMM2 (tf32 mma) with fused GRN transform on A-load:
//   out = ((h*scale + grn_b) @ w2) + b2 + feats
// BM=128, BN=128(full), BK=32; same warp layout as K2
// ---------------------------------------------------------------------------
__global__ __launch_bounds__(256) void k4_gemm2(
    const float* __restrict__ w2,   const float* __restrict__ b2,
    const float* __restrict__ grnb, const float* __restrict__ feats,
    float* __restrict__ out)
{
    __shared__ unsigned As[128][36];
    __shared__ unsigned Bs[32][136];

    const int tid = threadIdx.x;
    const int m0 = blockIdx.x * 128;
    const int lane = tid & 31, warpId = tid >> 5;
    const int wr = warpId & 3, wc = warpId >> 2;
    const int g = lane >> 2, tig = lane & 3;

    float acc[2][8][4] = {};

    for (int k0 = 0; k0 < 512; k0 += 32) {
        #pragma unroll
        for (int j = 0; j < 4; j++) {
            int idx = tid + j * 256;
            int r = idx >> 3, q = idx & 7;
            int gr = m0 + r;
            float4 v = make_float4(0.f, 0.f, 0.f, 0.f);
            if (gr < NS) {
                float4 hv = *(const float4*)(g_h + (size_t)gr * 512 + k0 + q * 4);
                float4 sc = *(const float4*)(g_scale + k0 + q * 4);
                float4 gb = *(const float4*)(grnb + k0 + q * 4);
                v.x = hv.x * sc.x + gb.x;
                v.y = hv.y * sc.y + gb.y;
                v.z = hv.z * sc.z + gb.z;
                v.w = hv.w * sc.w + gb.w;
            }
            *(uint4*)&As[r][q * 4] =
                make_uint4(f2tf32(v.x), f2tf32(v.y), f2tf32(v.z), f2tf32(v.w));
        }
        #pragma unroll
        for (int j = 0; j < 4; j++) {
            int idx = tid + j * 256;
            int kk = idx >> 5, q = idx & 31;
            float4 v = *(const float4*)(w2 + (size_t)(k0 + kk) * 128 + q * 4);
            *(uint4*)&Bs[kk][q * 4] =
                make_uint4(f2tf32(v.x), f2tf32(v.y), f2tf32(v.z), f2tf32(v.w));
        }
        __syncthreads();

        #pragma unroll
        for (int ks = 0; ks < 32; ks += 8) {
            unsigned bfr[8][2];
            #pragma unroll
            for (int j = 0; j < 8; j++) {
                int col = wc * 64 + j * 8 + g;
                bfr[j][0] = Bs[ks + tig][col];
                bfr[j][1] = Bs[ks + tig + 4][col];
            }
            #pragma unroll
            for (int i = 0; i < 2; i++) {
                int rb = wr * 32 + i * 16 + g;
                unsigned afr[4];
                afr[0] = As[rb][ks + tig];
                afr[1] = As[rb + 8][ks + tig];
                afr[2] = As[rb][ks + tig + 4];
                afr[3] = As[rb + 8][ks + tig + 4];
                #pragma unroll
                for (int j = 0; j < 8; j++) mma_tf32(acc[i][j], afr, bfr[j]);
            }
        }
        __syncthreads();
    }

    #pragma unroll
    for (int i = 0; i < 2; i++) {
        int r0r = m0 + wr * 32 + i * 16 + g;
        #pragma unroll
        for (int j = 0; j < 8; j++) {
            int cc = wc * 64 + j * 8 + 2 * tig;
            float b0v = b2[cc], b1v = b2[cc + 1];
            #pragma unroll
            for (int h = 0; h < 2; h++) {
                int rr = r0r + h * 8;
                if (rr < NS) {
                    out[(size_t)rr * 128 + cc] =
                        acc[i][j][2 * h + 0] + b0v + feats[(size_t)rr * 128 + cc];
                    out[(size_t)rr * 128 + cc + 1] =
                        acc[i][j][2 * h + 1] + b1v + feats[(size_t)rr * 128 + cc + 1];
                }
            }
        }
    }
}

// ---------------------------------------------------------------------------
extern "C" void kernel_launch(void* const* d_in, const int* in_sizes, int n_in,
                              void* d_out, int out_size)
{
    const float* feats = (const float*)d_in[0];
    const int*   nidx  = (const int*)  d_in[1];
    const float* dww   = (const float*)d_in[2];
    const float* dwb   = (const float*)d_in[3];
    const float* lng   = (const float*)d_in[4];
    const float* lnb   = (const float*)d_in[5];
    const float* w1    = (const float*)d_in[6];
    const float* b1    = (const float*)d_in[7];
    const float* grng  = (const float*)d_in[8];
    const float* grnb  = (const float*)d_in[9];
    const float* w2    = (const float*)d_in[10];
    const float* b2    = (const float*)d_in[11];
    float* out = (float*)d_out;

    k1_dwln<<<(NS + 7) / 8, 256>>>(feats, nidx, dww, dwb, lng, lnb);

    dim3 g2((NS + 127) / 128, H / 128);
    k2_gemm1<<<g2, 256>>>(w1, b1);

    k3_grn<<<1, H>>>(grng);

    k4_gemm2<<<(NS + 127) / 128, 256>>>(w2, b2, grnb, feats, out);
}

// round 4
// speedup vs baseline: 2.5884x; 1.2669x over previous
#include <cuda_runtime.h>
#include <math.h>

#define NS 100000
#define D  128
#define H  512
#define KK 343

// Scratch (device globals; no allocation allowed)
__device__ float g_xn[(size_t)NS * D];      // LN output (tf32-rounded), 51.2 MB
__device__ float g_h [(size_t)NS * H];      // GELU output (tf32-rounded), 204.8 MB
__device__ float g_gsum[H];
__device__ float g_scale[H];
__device__ float g_w1p[(size_t)D * H];      // tf32-rounded w1
__device__ float g_w2p[(size_t)H * D];      // tf32-rounded scale*w2
__device__ float g_c[D];                    // grn_b @ w2 (exact f32)

__device__ __forceinline__ unsigned f2tf32(float x) {
    unsigned r;
    asm("cvt.rna.tf32.f32 %0, %1;" : "=r"(r) : "f"(x));
    return r;
}
__device__ __forceinline__ float f2tf32f(float x) { return __uint_as_float(f2tf32(x)); }

__device__ __forceinline__ void mma_tf32(float* c, const unsigned* a, const unsigned* b) {
    asm volatile(
        "mma.sync.aligned.m16n8k8.row.col.f32.tf32.tf32.f32 "
        "{%0,%1,%2,%3}, {%4,%5,%6,%7}, {%8,%9}, {%0,%1,%2,%3};"
        : "+f"(c[0]), "+f"(c[1]), "+f"(c[2]), "+f"(c[3])
        : "r"(a[0]), "r"(a[1]), "r"(a[2]), "r"(a[3]), "r"(b[0]), "r"(b[1]));
}

__device__ __forceinline__ void cp16(float* dst, const float* src) {
    unsigned d = (unsigned)__cvta_generic_to_shared(dst);
    asm volatile("cp.async.cg.shared.global [%0], [%1], 16;" :: "r"(d), "l"(src));
}
__device__ __forceinline__ void cp_commit() { asm volatile("cp.async.commit_group;"); }
__device__ __forceinline__ void cp_wait1()  { asm volatile("cp.async.wait_group 1;"); }
__device__ __forceinline__ void cp_wait0()  { asm volatile("cp.async.wait_group 0;"); }

// Stage geometry (shared by both GEMMs): As[128][36] + Bs[32][136]
#define A_LD  36
#define B_LD  136
#define A_FLOATS (128 * A_LD)            // 4608
#define STG_FLOATS (A_FLOATS + 32 * B_LD) // 8960
#define SMEM_BYTES (2 * STG_FLOATS * 4)   // 71680

// ---------------------------------------------------------------------------
// K0: pre-round w1 to tf32
// ---------------------------------------------------------------------------
__global__ void k0_cvtw1(const float* __restrict__ w1)
{
    int i = (blockIdx.x * 256 + threadIdx.x) * 4;   // 64 blocks * 256 * 4 = 65536
    float4 v = *(const float4*)(w1 + i);
    float4 o = make_float4(f2tf32f(v.x), f2tf32f(v.y), f2tf32f(v.z), f2tf32f(v.w));
    *(float4*)(g_w1p + i) = o;
}

// ---------------------------------------------------------------------------
// K1: sparse depthwise conv + LayerNorm. One WARP per site, float4 per lane.
// Output is tf32-rounded so K2 can cp.async it raw.
// ---------------------------------------------------------------------------
__global__ __launch_bounds__(256) void k1_dwln(
    const float* __restrict__ feats, const int* __restrict__ nidx,
    const float* __restrict__ dww,   const float* __restrict__ dwb,
    const float* __restrict__ lng,   const float* __restrict__ lnb)
{
    const int tid  = threadIdx.x;
    const int lane = tid & 31, warp = tid >> 5;
    const int site = blockIdx.x * 8 + warp;

    if (blockIdx.x == 0) {
        if (tid < H) g_gsum[tid] = 0.f;
        if (tid + 256 < H) g_gsum[tid + 256] = 0.f;
    }

    __shared__ int s_list[8][KK];

    const int* row = nidx + (size_t)site * KK;
    int cnt = 0;
    #pragma unroll
    for (int base = 0; base < KK; base += 32) {
        int k  = base + lane;
        int id = (k < KK) ? row[k] : NS;
        bool v = (id != NS);
        unsigned m = __ballot_sync(0xffffffffu, v);
        if (v) s_list[warp][cnt + __popc(m & ((1u << lane) - 1u))] = (k << 17) | id;
        cnt += __popc(m);
    }
    __syncwarp();

    const int c4 = lane * 4;
    float4 acc = make_float4(0.f, 0.f, 0.f, 0.f);
    for (int j = 0; j < cnt; j++) {
        int kid = s_list[warp][j];            // warp-uniform
        int id  = kid & 0x1ffff;
        int k   = kid >> 17;
        float4 f = *(const float4*)(feats + (size_t)id * D + c4);
        float4 w = *(const float4*)(dww   + (size_t)k  * D + c4);
        acc.x += f.x * w.x; acc.y += f.y * w.y;
        acc.z += f.z * w.z; acc.w += f.w * w.w;
    }
    float4 bb = *(const float4*)(dwb + c4);
    float4 x = make_float4(acc.x + bb.x, acc.y + bb.y, acc.z + bb.z, acc.w + bb.w);

    float s  = x.x + x.y + x.z + x.w;
    float s2 = x.x * x.x + x.y * x.y + x.z * x.z + x.w * x.w;
    #pragma unroll
    for (int o = 16; o > 0; o >>= 1) {
        s  += __shfl_xor_sync(0xffffffffu, s,  o);
        s2 += __shfl_xor_sync(0xffffffffu, s2, o);
    }
    float mu  = s  * (1.f / 128.f);
    float var = s2 * (1.f / 128.f) - mu * mu;
    float inv = rsqrtf(var + 1e-6f);

    float4 gg = *(const float4*)(lng + c4);
    float4 be = *(const float4*)(lnb + c4);
    float4 o;
    o.x = f2tf32f((x.x - mu) * inv * gg.x + be.x);
    o.y = f2tf32f((x.y - mu) * inv * gg.y + be.y);
    o.z = f2tf32f((x.z - mu) * inv * gg.z + be.z);
    o.w = f2tf32f((x.w - mu) * inv * gg.w + be.w);
    *(float4*)(g_xn + (size_t)site * D + c4) = o;
}

// ---------------------------------------------------------------------------
// Shared GEMM mainloop body (BM=128, BN=128, BK=32, 8 warps 4x2, 32x64 warp
// tile). A and B already tf32-rounded in gmem; cp.async double-buffered.
// ---------------------------------------------------------------------------
__device__ __forceinline__ void gemm_issue(
    float* sm, int st, int tid, int m0, int k0,
    const float* __restrict__ Ag, int lda,     // A row stride (elements)
    const float* __restrict__ Bg, int ldb, int n0)
{
    float* As = sm + st * STG_FLOATS;
    float* Bs = As + A_FLOATS;
    #pragma unroll
    for (int j = 0; j < 4; j++) {
        int idx = tid + j * 256;
        int r = idx >> 3, q = idx & 7;
        int gr = m0 + r;
        if (gr < NS) cp16(&As[r * A_LD + q * 4], Ag + (size_t)gr * lda + k0 + q * 4);
    }
    #pragma unroll
    for (int j = 0; j < 4; j++) {
        int idx = tid + j * 256;
        int kk = idx >> 5, q = idx & 31;
        cp16(&Bs[kk * B_LD + q * 4], Bg + (size_t)(k0 + kk) * ldb + n0 + q * 4);
    }
    cp_commit();
}

__device__ __forceinline__ void gemm_compute(
    const float* sm, int st, int wr, int wc, int g, int tig,
    float acc[2][8][4])
{
    const unsigned* As = (const unsigned*)(sm + st * STG_FLOATS);
    const unsigned* Bs = As + A_FLOATS;
    #pragma unroll
    for (int ks = 0; ks < 32; ks += 8) {
        unsigned bfr[8][2];
        #pragma unroll
        for (int j = 0; j < 8; j++) {
            int col = wc * 64 + j * 8 + g;
            bfr[j][0] = Bs[(ks + tig) * B_LD + col];
            bfr[j][1] = Bs[(ks + tig + 4) * B_LD + col];
        }
        #pragma unroll
        for (int i = 0; i < 2; i++) {
            int rb = wr * 32 + i * 16 + g;
            unsigned afr[4];
            afr[0] = As[rb * A_LD + ks + tig];
            afr[1] = As[(rb + 8) * A_LD + ks + tig];
            afr[2] = As[rb * A_LD + ks + tig + 4];
            afr[3] = As[(rb + 8) * A_LD + ks + tig + 4];
            #pragma unroll
            for (int j = 0; j < 8; j++) mma_tf32(acc[i][j], afr, bfr[j]);
        }
    }
}

// ---------------------------------------------------------------------------
// K2: GEMM1: h = gelu(xn @ w1p + b1); stores tf32-rounded h + sum of h^2
// grid: 1D, n fastest (4 n-blocks share an A tile via L2)
// ---------------------------------------------------------------------------
__global__ __launch_bounds__(256, 2) void k2_gemm1(const float* __restrict__ b1)
{
    extern __shared__ float sm[];
    __shared__ float s_gsum[128];

    const int tid = threadIdx.x;
    const int n0 = (blockIdx.x & 3) * 128;
    const int m0 = (blockIdx.x >> 2) * 128;
    const int lane = tid & 31, warpId = tid >> 5;
    const int wr = warpId & 3, wc = warpId >> 2;
    const int g = lane >> 2, tig = lane & 3;

    if (tid < 128) s_gsum[tid] = 0.f;

    float acc[2][8][4] = {};

    gemm_issue(sm, 0, tid, m0, 0, g_xn, 128, g_w1p, 512, n0);
    #pragma unroll
    for (int t = 0; t < 4; t++) {
        if (t < 3) { gemm_issue(sm, (t + 1) & 1, tid, m0, (t + 1) * 32, g_xn, 128, g_w1p, 512, n0); cp_wait1(); }
        else cp_wait0();
        __syncthreads();
        gemm_compute(sm, t & 1, wr, wc, g, tig, acc);
        __syncthreads();
    }

    // epilogue: bias + exact GELU, store rounded h, square-sum reduce
    float p[8][2] = {};
    #pragma unroll
    for (int i = 0; i < 2; i++) {
        int r0r = m0 + wr * 32 + i * 16 + g;
        #pragma unroll
        for (int j = 0; j < 8; j++) {
            int cc = n0 + wc * 64 + j * 8 + 2 * tig;
            float b0v = b1[cc], b1v = b1[cc + 1];
            #pragma unroll
            for (int h = 0; h < 2; h++) {
                int rr = r0r + h * 8;
                if (rr < NS) {
                    float v0 = acc[i][j][2 * h + 0] + b0v;
                    float v1 = acc[i][j][2 * h + 1] + b1v;
                    float g0 = 0.5f * v0 * (1.f + erff(v0 * 0.70710678118654752f));
                    float g1 = 0.5f * v1 * (1.f + erff(v1 * 0.70710678118654752f));
                    g_h[(size_t)rr * 512 + cc]     = f2tf32f(g0);
                    g_h[(size_t)rr * 512 + cc + 1] = f2tf32f(g1);
                    p[j][0] += g0 * g0;
                    p[j][1] += g1 * g1;
                }
            }
        }
    }
    #pragma unroll
    for (int j = 0; j < 8; j++) {
        #pragma unroll
        for (int c = 0; c < 2; c++) {
            #pragma unroll
            for (int o = 4; o < 32; o <<= 1)
                p[j][c] += __shfl_xor_sync(0xffffffffu, p[j][c], o);
        }
    }
    if (lane < 4) {
        #pragma unroll
        for (int j = 0; j < 8; j++) {
            atomicAdd(&s_gsum[wc * 64 + j * 8 + 2 * lane],     p[j][0]);
            atomicAdd(&s_gsum[wc * 64 + j * 8 + 2 * lane + 1], p[j][1]);
        }
    }
    __syncthreads();
    if (tid < 128) atomicAdd(&g_gsum[n0 + tid], s_gsum[tid]);
}

// ---------------------------------------------------------------------------
// K3: GRN scale + zero g_c
// ---------------------------------------------------------------------------
__global__ void k3_grn(const float* __restrict__ grng)
{
    const int c = threadIdx.x;       // 512 threads
    const int lane = c & 31, warp = c >> 5;
    float gx = sqrtf(g_gsum[c]);
    if (c < D) g_c[c] = 0.f;

    __shared__ float ws[16];
    __shared__ float s_tot;
    float s = gx;
    #pragma unroll
    for (int o = 16; o > 0; o >>= 1) s += __shfl_xor_sync(0xffffffffu, s, o);
    if (lane == 0) ws[warp] = s;
    __syncthreads();
    if (c == 0) {
        float t = 0.f;
        #pragma unroll
        for (int i = 0; i < 16; i++) t += ws[i];
        s_tot = t;
    }
    __syncthreads();
    float mean = s_tot * (1.f / 512.f);
    g_scale[c] = grng[c] * (gx / (mean + 1e-6f)) + 1.f;
}

// ---------------------------------------------------------------------------
// K3w: fold GRN into B of GEMM2: w2p = round(scale_k * w2[k][j]);
//      c_j = sum_k grn_b[k] * w2[k][j]
// 128 blocks x 128 threads; block b handles k rows 4b..4b+3
// ---------------------------------------------------------------------------
__global__ void k3w_fold(const float* __restrict__ w2, const float* __restrict__ grnb)
{
    const int j = threadIdx.x;
    float csum = 0.f;
    #pragma unroll
    for (int r = 0; r < 4; r++) {
        int k = blockIdx.x * 4 + r;
        float w = w2[(size_t)k * 128 + j];
        g_w2p[(size_t)k * 128 + j] = f2tf32f(g_scale[k] * w);
        csum += grnb[k] * w;
    }
    atomicAdd(&g_c[j], csum);
}

// ---------------------------------------------------------------------------
// K4: GEMM2: out = h @ w2p + (b2 + c) + feats
// ---------------------------------------------------------------------------
__global__ __launch_bounds__(256, 2) void k4_gemm2(
    const float* __restrict__ b2, const float* __restrict__ feats,
    float* __restrict__ out)
{
    extern __shared__ float sm[];

    const int tid = threadIdx.x;
    const int m0 = blockIdx.x * 128;
    const int lane = tid & 31, warpId = tid >> 5;
    const int wr = warpId & 3, wc = warpId >> 2;
    const int g = lane >> 2, tig = lane & 3;

    float acc[2][8][4] = {};

    gemm_issue(sm, 0, tid, m0, 0, g_h, 512, g_w2p, 128, 0);
    #pragma unroll
    for (int t = 0; t < 16; t++) {
        if (t < 15) { gemm_issue(sm, (t + 1) & 1, tid, m0, (t + 1) * 32, g_h, 512, g_w2p, 128, 0); cp_wait1(); }
        else cp_wait0();
        __syncthreads();
        gemm_compute(sm, t & 1, wr, wc, g, tig, acc);
        __syncthreads();
    }

    #pragma unroll
    for (int i = 0; i < 2; i++) {
        int r0r = m0 + wr * 32 + i * 16 + g;
        #pragma unroll
        for (int j = 0; j < 8; j++) {
            int cc = wc * 64 + j * 8 + 2 * tig;
            float b0v = b2[cc] + g_c[cc];
            float b1v = b2[cc + 1] + g_c[cc + 1];
            #pragma unroll
            for (int h = 0; h < 2; h++) {
                int rr = r0r + h * 8;
                if (rr < NS) {
                    out[(size_t)rr * 128 + cc] =
                        acc[i][j][2 * h + 0] + b0v + feats[(size_t)rr * 128 + cc];
                    out[(size_t)rr * 128 + cc + 1] =
                        acc[i][j][2 * h + 1] + b1v + feats[(size_t)rr * 128 + cc + 1];
                }
            }
        }
    }
}

// ---------------------------------------------------------------------------
extern "C" void kernel_launch(void* const* d_in, const int* in_sizes, int n_in,
                              void* d_out, int out_size)
{
    const float* feats = (const float*)d_in[0];
    const int*   nidx  = (const int*)  d_in[1];
    const float* dww   = (const float*)d_in[2];
    const float* dwb   = (const float*)d_in[3];
    const float* lng   = (const float*)d_in[4];
    const float* lnb   = (const float*)d_in[5];
    const float* w1    = (const float*)d_in[6];
    const float* b1    = (const float*)d_in[7];
    const float* grng  = (const float*)d_in[8];
    const float* grnb  = (const float*)d_in[9];
    const float* w2    = (const float*)d_in[10];
    const float* b2    = (const float*)d_in[11];
    float* out = (float*)d_out;

    cudaFuncSetAttribute(k2_gemm1, cudaFuncAttributeMaxDynamicSharedMemorySize, SMEM_BYTES);
    cudaFuncSetAttribute(k4_gemm2, cudaFuncAttributeMaxDynamicSharedMemorySize, SMEM_BYTES);

    k0_cvtw1<<<64, 256>>>(w1);
    k1_dwln<<<(NS + 7) / 8, 256>>>(feats, nidx, dww, dwb, lng, lnb);

    k2_gemm1<<<((NS + 127) / 128) * 4, 256, SMEM_BYTES>>>(b1);

    k3_grn<<<1, H>>>(grng);
    k3w_fold<<<128, 128>>>(w2, grnb);

    k4_gemm2<<<(NS + 127) / 128, 256, SMEM_BYTES>>>(b2, feats, out);
}

// round 7
// speedup vs baseline: 3.4267x; 1.3238x over previous
#include <cuda_runtime.h>
#include <cuda_fp16.h>
#include <math.h>

#define NS 100000
#define D  128
#define H  512
#define KK 343

// Scratch (device globals; no allocation allowed)
__device__ __half g_xnh[(size_t)NS * D];    // LN output (fp16), 25.6 MB
__device__ __half g_hh [(size_t)NS * H];    // GELU output (fp16), 102.4 MB
__device__ float  g_gsum[H];
__device__ float  g_scale[H];
__device__ __half g_w1p[(size_t)H * D];     // w1 transposed: [n=512][k=128] fp16
__device__ __half g_w2p[(size_t)D * H];     // scale*w2 transposed: [n=128][k=512] fp16
__device__ float  g_c[D];                   // grn_b @ w2 (exact f32)

__device__ __forceinline__ void mma_f16(float* c, const unsigned* a, const unsigned* b) {
    asm volatile(
        "mma.sync.aligned.m16n8k16.row.col.f32.f16.f16.f32 "
        "{%0,%1,%2,%3}, {%4,%5,%6,%7}, {%8,%9}, {%0,%1,%2,%3};"
        : "+f"(c[0]), "+f"(c[1]), "+f"(c[2]), "+f"(c[3])
        : "r"(a[0]), "r"(a[1]), "r"(a[2]), "r"(a[3]), "r"(b[0]), "r"(b[1]));
}

__device__ __forceinline__ void cp16(__half* dst, const __half* src) {
    unsigned d = (unsigned)__cvta_generic_to_shared(dst);
    asm volatile("cp.async.cg.shared.global [%0], [%1], 16;" :: "r"(d), "l"(src));
}
__device__ __forceinline__ void cp_commit() { asm volatile("cp.async.commit_group;"); }
__device__ __forceinline__ void cp_wait1()  { asm volatile("cp.async.wait_group 1;"); }
__device__ __forceinline__ void cp_wait0()  { asm volatile("cp.async.wait_group 0;"); }

// Stage geometry: As[128][40] halves + Bs[128][40] halves (BK=32, pad 8)
#define BK    32
#define LDH   40
#define A_HALFS (128 * LDH)                 // 5120
#define STG_HALFS (2 * A_HALFS)             // 10240 halves = 20480 B
#define N_STG 3
#define SMEM_BYTES (N_STG * STG_HALFS * 2)  // 61440

// ---------------------------------------------------------------------------
// K0: transpose + convert w1 -> g_w1p[n][k] fp16.  512 blocks x 128 threads.
// ---------------------------------------------------------------------------
__global__ void k0_cvtw1(const float* __restrict__ w1)
{
    const int n = blockIdx.x;     // 0..511
    const int k = threadIdx.x;    // 0..127
    g_w1p[(size_t)n * 128 + k] = __float2half_rn(w1[(size_t)k * 512 + n]);
}

// ---------------------------------------------------------------------------
// K1: sparse depthwise conv + LayerNorm. One WARP per site, float4 per lane.
// Writes fp16 output.
// ---------------------------------------------------------------------------
__global__ __launch_bounds__(256) void k1_dwln(
    const float* __restrict__ feats, const int* __restrict__ nidx,
    const float* __restrict__ dww,   const float* __restrict__ dwb,
    const float* __restrict__ lng,   const float* __restrict__ lnb)
{
    const int tid  = threadIdx.x;
    const int lane = tid & 31, warp = tid >> 5;
    const int site = blockIdx.x * 8 + warp;

    if (blockIdx.x == 0) {
        if (tid < H) g_gsum[tid] = 0.f;
        if (tid + 256 < H) g_gsum[tid + 256] = 0.f;
    }

    __shared__ int s_list[8][KK];

    const int* row = nidx + (size_t)site * KK;
    int cnt = 0;
    #pragma unroll
    for (int base = 0; base < KK; base += 32) {
        int k  = base + lane;
        int id = (k < KK) ? row[k] : NS;
        bool v = (id != NS);
        unsigned m = __ballot_sync(0xffffffffu, v);
        if (v) s_list[warp][cnt + __popc(m & ((1u << lane) - 1u))] = (k << 17) | id;
        cnt += __popc(m);
    }
    __syncwarp();

    const int c4 = lane * 4;
    float4 acc = make_float4(0.f, 0.f, 0.f, 0.f);
    for (int j = 0; j < cnt; j++) {
        int kid = s_list[warp][j];            // warp-uniform
        int id  = kid & 0x1ffff;
        int k   = kid >> 17;
        float4 f = *(const float4*)(feats + (size_t)id * D + c4);
        float4 w = *(const float4*)(dww   + (size_t)k  * D + c4);
        acc.x += f.x * w.x; acc.y += f.y * w.y;
        acc.z += f.z * w.z; acc.w += f.w * w.w;
    }
    float4 bb = *(const float4*)(dwb + c4);
    float4 x = make_float4(acc.x + bb.x, acc.y + bb.y, acc.z + bb.z, acc.w + bb.w);

    float s  = x.x + x.y + x.z + x.w;
    float s2 = x.x * x.x + x.y * x.y + x.z * x.z + x.w * x.w;
    #pragma unroll
    for (int o = 16; o > 0; o >>= 1) {
        s  += __shfl_xor_sync(0xffffffffu, s,  o);
        s2 += __shfl_xor_sync(0xffffffffu, s2, o);
    }
    float mu  = s  * (1.f / 128.f);
    float var = s2 * (1.f / 128.f) - mu * mu;
    float inv = rsqrtf(var + 1e-6f);

    float4 gg = *(const float4*)(lng + c4);
    float4 be = *(const float4*)(lnb + c4);
    __half2 h01 = __floats2half2_rn((x.x - mu) * inv * gg.x + be.x,
                                    (x.y - mu) * inv * gg.y + be.y);
    __half2 h23 = __floats2half2_rn((x.z - mu) * inv * gg.z + be.z,
                                    (x.w - mu) * inv * gg.w + be.w);
    uint2 packed;
    packed.x = *(const unsigned*)&h01;
    packed.y = *(const unsigned*)&h23;
    *(uint2*)(g_xnh + (size_t)site * D + c4) = packed;
}

// ---------------------------------------------------------------------------
// GEMM mainloop (BM=128, BN=128, BK=32, fp16 m16n8k16, 8 warps 4x2, 32x64
// warp tile). B stored transposed [n][k] in gmem.
// ---------------------------------------------------------------------------
__device__ __forceinline__ void gemm_issue(
    __half* sm, int st, int tid, int m0, int k0,
    const __half* __restrict__ Ag, int lda,
    const __half* __restrict__ Bg, int ldb)
{
    __half* As = sm + st * STG_HALFS;
    __half* Bs = As + A_HALFS;
    #pragma unroll
    for (int j = 0; j < 2; j++) {
        int idx = tid + j * 256;
        int r = idx >> 2, q = idx & 3;
        int gr = m0 + r;
        if (gr < NS) cp16(&As[r * LDH + q * 8], Ag + (size_t)gr * lda + k0 + q * 8);
    }
    #pragma unroll
    for (int j = 0; j < 2; j++) {
        int idx = tid + j * 256;
        int nr = idx >> 2, q = idx & 3;
        cp16(&Bs[nr * LDH + q * 8], Bg + (size_t)nr * ldb + k0 + q * 8);
    }
    cp_commit();
}

__device__ __forceinline__ void gemm_compute(
    const __half* sm, int st, int wr, int wc, int g, int tig,
    float acc[2][8][4])
{
    const __half* As = sm + st * STG_HALFS;
    const __half* Bs = As + A_HALFS;
    #pragma unroll
    for (int kb = 0; kb < BK; kb += 16) {
        unsigned bfr[8][2];
        #pragma unroll
        for (int j = 0; j < 8; j++) {
            int col = wc * 64 + j * 8 + g;
            bfr[j][0] = *(const unsigned*)&Bs[col * LDH + kb + 2 * tig];
            bfr[j][1] = *(const unsigned*)&Bs[col * LDH + kb + 2 * tig + 8];
        }
        #pragma unroll
        for (int i = 0; i < 2; i++) {
            int rb = wr * 32 + i * 16 + g;
            unsigned afr[4];
            afr[0] = *(const unsigned*)&As[rb * LDH + kb + 2 * tig];
            afr[1] = *(const unsigned*)&As[(rb + 8) * LDH + kb + 2 * tig];
            afr[2] = *(const unsigned*)&As[rb * LDH + kb + 2 * tig + 8];
            afr[3] = *(const unsigned*)&As[(rb + 8) * LDH + kb + 2 * tig + 8];
            #pragma unroll
            for (int j = 0; j < 8; j++) mma_f16(acc[i][j], afr, bfr[j]);
        }
    }
}

// ---------------------------------------------------------------------------
// K2: GEMM1: h = gelu(xn @ w1 + b1); stores fp16 h + per-channel sum h^2
// ---------------------------------------------------------------------------
__global__ __launch_bounds__(256, 2) void k2_gemm1(const float* __restrict__ b1)
{
    extern __shared__ __half sm[];
    __shared__ float s_gsum[128];

    const int tid = threadIdx.x;
    const int n0 = (blockIdx.x & 3) * 128;
    const int m0 = (blockIdx.x >> 2) * 128;
    const int lane = tid & 31, warpId = tid >> 5;
    const int wr = warpId & 3, wc = warpId >> 2;
    const int g = lane >> 2, tig = lane & 3;

    if (tid < 128) s_gsum[tid] = 0.f;

    const __half* Bg = g_w1p + (size_t)n0 * 128;
    float acc[2][8][4] = {};

    const int T = 128 / BK;   // 4
    gemm_issue(sm, 0, tid, m0, 0, g_xnh, 128, Bg, 128);
    gemm_issue(sm, 1, tid, m0, BK, g_xnh, 128, Bg, 128);
    #pragma unroll
    for (int t = 0; t < T; t++) {
        if (t < T - 1) cp_wait1(); else cp_wait0();
        __syncthreads();
        if (t + 2 < T)
            gemm_issue(sm, (t + 2) % N_STG, tid, m0, (t + 2) * BK, g_xnh, 128, Bg, 128);
        gemm_compute(sm, t % N_STG, wr, wc, g, tig, acc);
    }

    // epilogue: bias + exact GELU, store fp16 h, square-sum reduce
    float p[8][2] = {};
    #pragma unroll
    for (int i = 0; i < 2; i++) {
        int r0r = m0 + wr * 32 + i * 16 + g;
        #pragma unroll
        for (int j = 0; j < 8; j++) {
            int cc = n0 + wc * 64 + j * 8 + 2 * tig;
            float b0v = b1[cc], b1v = b1[cc + 1];
            #pragma unroll
            for (int h = 0; h < 2; h++) {
                int rr = r0r + h * 8;
                if (rr < NS) {
                    float v0 = acc[i][j][2 * h + 0] + b0v;
                    float v1 = acc[i][j][2 * h + 1] + b1v;
                    float g0 = 0.5f * v0 * (1.f + erff(v0 * 0.70710678118654752f));
                    float g1 = 0.5f * v1 * (1.f + erff(v1 * 0.70710678118654752f));
                    *(__half2*)(g_hh + (size_t)rr * 512 + cc) = __floats2half2_rn(g0, g1);
                    p[j][0] += g0 * g0;
                    p[j][1] += g1 * g1;
                }
            }
        }
    }
    #pragma unroll
    for (int j = 0; j < 8; j++) {
        #pragma unroll
        for (int c = 0; c < 2; c++) {
            #pragma unroll
            for (int o = 4; o < 32; o <<= 1)
                p[j][c] += __shfl_xor_sync(0xffffffffu, p[j][c], o);
        }
    }
    if (lane < 4) {
        #pragma unroll
        for (int j = 0; j < 8; j++) {
            atomicAdd(&s_gsum[wc * 64 + j * 8 + 2 * lane],     p[j][0]);
            atomicAdd(&s_gsum[wc * 64 + j * 8 + 2 * lane + 1], p[j][1]);
        }
    }
    __syncthreads();
    if (tid < 128) atomicAdd(&g_gsum[n0 + tid], s_gsum[tid]);
}

// ---------------------------------------------------------------------------
// K3: GRN scale
// ---------------------------------------------------------------------------
__global__ void k3_grn(const float* __restrict__ grng)
{
    const int c = threadIdx.x;       // 512 threads
    const int lane = c & 31, warp = c >> 5;
    float gx = sqrtf(g_gsum[c]);

    __shared__ float ws[16];
    __shared__ float s_tot;
    float s = gx;
    #pragma unroll
    for (int o = 16; o > 0; o >>= 1) s += __shfl_xor_sync(0xffffffffu, s, o);
    if (lane == 0) ws[warp] = s;
    __syncthreads();
    if (c == 0) {
        float t = 0.f;
        #pragma unroll
        for (int i = 0; i < 16; i++) t += ws[i];
        s_tot = t;
    }
    __syncthreads();
    float mean = s_tot * (1.f / 512.f);
    g_scale[c] = grng[c] * (gx / (mean + 1e-6f)) + 1.f;
}

// ---------------------------------------------------------------------------
// K3w: fold GRN into transposed B: w2p[n][k] = fp16(scale_k * w2[k][n]);
//      c_n = sum_k grn_b[k] * w2[k][n].  128 blocks (n) x 512 threads (k).
// ---------------------------------------------------------------------------
__global__ __launch_bounds__(512) void k3w_fold(
    const float* __restrict__ w2, const float* __restrict__ grnb)
{
    const int n = blockIdx.x;
    const int k = threadIdx.x;
    const int lane = k & 31, warp = k >> 5;
    float w = w2[(size_t)k * 128 + n];
    g_w2p[(size_t)n * 512 + k] = __float2half_rn(g_scale[k] * w);

    float s = grnb[k] * w;
    __shared__ float ws[16];
    #pragma unroll
    for (int o = 16; o > 0; o >>= 1) s += __shfl_xor_sync(0xffffffffu, s, o);
    if (lane == 0) ws[warp] = s;
    __syncthreads();
    if (k == 0) {
        float t = 0.f;
        #pragma unroll
        for (int i = 0; i < 16; i++) t += ws[i];
        g_c[n] = t;
    }
}

// ---------------------------------------------------------------------------
// K4: GEMM2: out = h @ w2p + (b2 + c) + feats
// ---------------------------------------------------------------------------
__global__ __launch_bounds__(256, 2) void k4_gemm2(
    const float* __restrict__ b2, const float* __restrict__ feats,
    float* __restrict__ out)
{
    extern __shared__ __half sm[];

    const int tid = threadIdx.x;
    const int m0 = blockIdx.x * 128;
    const int lane = tid & 31, warpId = tid >> 5;
    const int wr = warpId & 3, wc = warpId >> 2;
    const int g = lane >> 2, tig = lane & 3;

    float acc[2][8][4] = {};

    const int T = 512 / BK;   // 16
    gemm_issue(sm, 0, tid, m0, 0, g_hh, 512, g_w2p, 512);
    gemm_issue(sm, 1, tid, m0, BK, g_hh, 512, g_w2p, 512);
    #pragma unroll
    for (int t = 0; t < T; t++) {
        if (t < T - 1) cp_wait1(); else cp_wait0();
        __syncthreads();
        if (t + 2 < T)
            gemm_issue(sm, (t + 2) % N_STG, tid, m0, (t + 2) * BK, g_hh, 512, g_w2p, 512);
        gemm_compute(sm, t % N_STG, wr, wc, g, tig, acc);
    }

    #pragma unroll
    for (int i = 0; i < 2; i++) {
        int r0r = m0 + wr * 32 + i * 16 + g;
        #pragma unroll
        for (int j = 0; j < 8; j++) {
            int cc = wc * 64 + j * 8 + 2 * tig;
            float b0v = b2[cc] + g_c[cc];
            float b1v = b2[cc + 1] + g_c[cc + 1];
            #pragma unroll
            for (int h = 0; h < 2; h++) {
                int rr = r0r + h * 8;
                if (rr < NS) {
                    out[(size_t)rr * 128 + cc] =
                        acc[i][j][2 * h + 0] + b0v + feats[(size_t)rr * 128 + cc];
                    out[(size_t)rr * 128 + cc + 1] =
                        acc[i][j][2 * h + 1] + b1v + feats[(size_t)rr * 128 + cc + 1];
                }
            }
        }
    }
}

// ---------------------------------------------------------------------------
extern "C" void kernel_launch(void* const* d_in, const int* in_sizes, int n_in,
                              void* d_out, int out_size)
{
    const float* feats = (const float*)d_in[0];
    const int*   nidx  = (const int*)  d_in[1];
    const float* dww   = (const float*)d_in[2];
    const float* dwb   = (const float*)d_in[3];
    const float* lng   = (const float*)d_in[4];
    const float* lnb   = (const float*)d_in[5];
    const float* w1    = (const float*)d_in[6];
    const float* b1    = (const float*)d_in[7];
    const float* grng  = (const float*)d_in[8];
    const float* grnb  = (const float*)d_in[9];
    const float* w2    = (const float*)d_in[10];
    const float* b2    = (const float*)d_in[11];
    float* out = (float*)d_out;

    cudaFuncSetAttribute(k2_gemm1, cudaFuncAttributeMaxDynamicSharedMemorySize, SMEM_BYTES);
    cudaFuncSetAttribute(k4_gemm2, cudaFuncAttributeMaxDynamicSharedMemorySize, SMEM_BYTES);

    k0_cvtw1<<<512, 128>>>(w1);
    k1_dwln<<<(NS + 7) / 8, 256>>>(feats, nidx, dww, dwb, lng, lnb);

    k2_gemm1<<<((NS + 127) / 128) * 4, 256, SMEM_BYTES>>>(b1);

    k3_grn<<<1, H>>>(grng);
    k3w_fold<<<128, 512>>>(w2, grnb);

    k4_gemm2<<<(NS + 127) / 128, 256, SMEM_BYTES>>>(b2, feats, out);
}

// round 8
// speedup vs baseline: 3.4320x; 1.0015x over previous
#include <cuda_runtime.h>
#include <cuda_fp16.h>
#include <math.h>

#define NS 100000
#define D  128
#define H  512
#define KK 343

// Scratch (device globals; no allocation allowed)
__device__ __half g_fh [(size_t)NS * D];    // feats fp16, 25.6 MB
__device__ __half g_dwh[(size_t)KK * D];    // dw_w fp16
__device__ __half g_xnh[(size_t)NS * D];    // LN output (fp16), 25.6 MB
__device__ __half g_hh [(size_t)NS * H];    // GELU output (fp16), 102.4 MB
__device__ float  g_gsum[H];
__device__ float  g_scale[H];
__device__ __half g_w1p[(size_t)H * D];     // w1 transposed: [n=512][k=128] fp16
__device__ __half g_w2p[(size_t)D * H];     // scale*w2 transposed: [n=128][k=512] fp16
__device__ float  g_c[D];                   // grn_b @ w2 (exact f32)

__device__ __forceinline__ void mma_f16(float* c, const unsigned* a, const unsigned* b) {
    asm volatile(
        "mma.sync.aligned.m16n8k16.row.col.f32.f16.f16.f32 "
        "{%0,%1,%2,%3}, {%4,%5,%6,%7}, {%8,%9}, {%0,%1,%2,%3};"
        : "+f"(c[0]), "+f"(c[1]), "+f"(c[2]), "+f"(c[3])
        : "r"(a[0]), "r"(a[1]), "r"(a[2]), "r"(a[3]), "r"(b[0]), "r"(b[1]));
}

__device__ __forceinline__ void ldsm4(unsigned* r, const __half* p) {
    unsigned a = (unsigned)__cvta_generic_to_shared(p);
    asm volatile("ldmatrix.sync.aligned.m8n8.x4.shared.b16 {%0,%1,%2,%3}, [%4];"
        : "=r"(r[0]), "=r"(r[1]), "=r"(r[2]), "=r"(r[3]) : "r"(a));
}

__device__ __forceinline__ void cp16(__half* dst, const __half* src) {
    unsigned d = (unsigned)__cvta_generic_to_shared(dst);
    asm volatile("cp.async.cg.shared.global [%0], [%1], 16;" :: "r"(d), "l"(src));
}
__device__ __forceinline__ void cp_commit() { asm volatile("cp.async.commit_group;"); }
__device__ __forceinline__ void cp_wait1()  { asm volatile("cp.async.wait_group 1;"); }
__device__ __forceinline__ void cp_wait0()  { asm volatile("cp.async.wait_group 0;"); }

// Stage geometry: As[128][72] + Bs[128][72] halves (BK=64, pad 8)
#define BK    64
#define LDH   72
#define A_HALFS (128 * LDH)                 // 9216
#define STG_HALFS (2 * A_HALFS)             // 18432 halves
#define N_STG 3
#define SMEM_BYTES (N_STG * STG_HALFS * 2)  // 110592

// ---------------------------------------------------------------------------
// K0 family: format conversions
// ---------------------------------------------------------------------------
__global__ void k0_cvtw1(const float* __restrict__ w1)
{
    const int n = blockIdx.x;     // 0..511
    const int k = threadIdx.x;    // 0..127
    g_w1p[(size_t)n * 128 + k] = __float2half_rn(w1[(size_t)k * 512 + n]);
}

__global__ void k0_cvtfeats(const float* __restrict__ feats)
{
    size_t i = ((size_t)blockIdx.x * 256 + threadIdx.x) * 4;  // 12500 blocks
    float4 v = *(const float4*)(feats + i);
    __half2 a = __floats2half2_rn(v.x, v.y);
    __half2 b = __floats2half2_rn(v.z, v.w);
    uint2 p;
    p.x = *(const unsigned*)&a;
    p.y = *(const unsigned*)&b;
    *(uint2*)(g_fh + i) = p;
}

__global__ void k0_cvtdww(const float* __restrict__ dww)
{
    int i = (blockIdx.x * 256 + threadIdx.x) * 4;
    if (i < KK * D) {
        float4 v = *(const float4*)(dww + i);
        __half2 a = __floats2half2_rn(v.x, v.y);
        __half2 b = __floats2half2_rn(v.z, v.w);
        uint2 p;
        p.x = *(const unsigned*)&a;
        p.y = *(const unsigned*)&b;
        *(uint2*)(g_dwh + i) = p;
    }
}

// ---------------------------------------------------------------------------
// K1: sparse depthwise conv + LayerNorm. One WARP per site, 4 channels/lane.
// Gathers fp16 feats/weights (half L2 traffic), accumulates fp32.
// ---------------------------------------------------------------------------
__global__ __launch_bounds__(256) void k1_dwln(
    const int* __restrict__ nidx, const float* __restrict__ dwb,
    const float* __restrict__ lng, const float* __restrict__ lnb)
{
    const int tid  = threadIdx.x;
    const int lane = tid & 31, warp = tid >> 5;
    const int site = blockIdx.x * 8 + warp;

    if (blockIdx.x == 0) {
        if (tid < H) g_gsum[tid] = 0.f;
        if (tid + 256 < H) g_gsum[tid + 256] = 0.f;
    }

    __shared__ int s_list[8][KK];

    const int* row = nidx + (size_t)site * KK;
    int cnt = 0;
    #pragma unroll
    for (int base = 0; base < KK; base += 32) {
        int k  = base + lane;
        int id = (k < KK) ? row[k] : NS;
        bool v = (id != NS);
        unsigned m = __ballot_sync(0xffffffffu, v);
        if (v) s_list[warp][cnt + __popc(m & ((1u << lane) - 1u))] = (k << 17) | id;
        cnt += __popc(m);
    }
    __syncwarp();

    const int c4 = lane * 4;
    float4 acc = make_float4(0.f, 0.f, 0.f, 0.f);
    for (int j = 0; j < cnt; j++) {
        int kid = s_list[warp][j];            // warp-uniform
        int id  = kid & 0x1ffff;
        int k   = kid >> 17;
        uint2 f = *(const uint2*)(g_fh  + (size_t)id * D + c4);
        uint2 w = *(const uint2*)(g_dwh + (size_t)k  * D + c4);
        float2 f0 = __half22float2(*(const __half2*)&f.x);
        float2 f1 = __half22float2(*(const __half2*)&f.y);
        float2 w0 = __half22float2(*(const __half2*)&w.x);
        float2 w1v = __half22float2(*(const __half2*)&w.y);
        acc.x += f0.x * w0.x;  acc.y += f0.y * w0.y;
        acc.z += f1.x * w1v.x; acc.w += f1.y * w1v.y;
    }
    float4 bb = *(const float4*)(dwb + c4);
    float4 x = make_float4(acc.x + bb.x, acc.y + bb.y, acc.z + bb.z, acc.w + bb.w);

    float s  = x.x + x.y + x.z + x.w;
    float s2 = x.x * x.x + x.y * x.y + x.z * x.z + x.w * x.w;
    #pragma unroll
    for (int o = 16; o > 0; o >>= 1) {
        s  += __shfl_xor_sync(0xffffffffu, s,  o);
        s2 += __shfl_xor_sync(0xffffffffu, s2, o);
    }
    float mu  = s  * (1.f / 128.f);
    float var = s2 * (1.f / 128.f) - mu * mu;
    float inv = rsqrtf(var + 1e-6f);

    float4 gg = *(const float4*)(lng + c4);
    float4 be = *(const float4*)(lnb + c4);
    __half2 h01 = __floats2half2_rn((x.x - mu) * inv * gg.x + be.x,
                                    (x.y - mu) * inv * gg.y + be.y);
    __half2 h23 = __floats2half2_rn((x.z - mu) * inv * gg.z + be.z,
                                    (x.w - mu) * inv * gg.w + be.w);
    uint2 packed;
    packed.x = *(const unsigned*)&h01;
    packed.y = *(const unsigned*)&h23;
    *(uint2*)(g_xnh + (size_t)site * D + c4) = packed;
}

// ---------------------------------------------------------------------------
// GEMM mainloop (BM=128, BN=128, BK=64, fp16 m16n8k16, 8 warps 4x2, 32x64
// warp tile, ldmatrix fragment loads). B stored transposed [n][k] in gmem.
// ---------------------------------------------------------------------------
__device__ __forceinline__ void gemm_issue(
    __half* sm, int st, int tid, int m0, int k0,
    const __half* __restrict__ Ag, int lda,
    const __half* __restrict__ Bg, int ldb)
{
    __half* As = sm + st * STG_HALFS;
    __half* Bs = As + A_HALFS;
    #pragma unroll
    for (int j = 0; j < 4; j++) {
        int idx = tid + j * 256;
        int r = idx >> 3, q = idx & 7;
        int gr = m0 + r;
        if (gr < NS) cp16(&As[r * LDH + q * 8], Ag + (size_t)gr * lda + k0 + q * 8);
    }
    #pragma unroll
    for (int j = 0; j < 4; j++) {
        int idx = tid + j * 256;
        int nr = idx >> 3, q = idx & 7;
        cp16(&Bs[nr * LDH + q * 8], Bg + (size_t)nr * ldb + k0 + q * 8);
    }
    cp_commit();
}

__device__ __forceinline__ void gemm_compute(
    const __half* sm, int st, int wr, int wc, int lane,
    float acc[2][8][4])
{
    const __half* As = sm + st * STG_HALFS;
    const __half* Bs = As + A_HALFS;
    #pragma unroll
    for (int kb = 0; kb < BK; kb += 16) {
        // B fragments: 4 ldmatrix.x4 -> 8 n8-blocks x 2 k-halves
        unsigned bfr[8][2];
        #pragma unroll
        for (int jj = 0; jj < 4; jj++) {
            int n = wc * 64 + jj * 16 + (lane & 7) + ((lane >> 4) << 3);
            int c = kb + (((lane >> 3) & 1) << 3);
            unsigned t[4];
            ldsm4(t, &Bs[n * LDH + c]);
            bfr[2 * jj][0] = t[0]; bfr[2 * jj][1] = t[1];
            bfr[2 * jj + 1][0] = t[2]; bfr[2 * jj + 1][1] = t[3];
        }
        #pragma unroll
        for (int i = 0; i < 2; i++) {
            int r = wr * 32 + i * 16 + (lane & 15);
            int c = kb + ((lane >> 4) << 3);
            unsigned afr[4];
            ldsm4(afr, &As[r * LDH + c]);
            #pragma unroll
            for (int j = 0; j < 8; j++) mma_f16(acc[i][j], afr, bfr[j]);
        }
    }
}

// ---------------------------------------------------------------------------
// K2: GEMM1: h = gelu(xn @ w1 + b1); stores fp16 h + per-channel sum h^2
// ---------------------------------------------------------------------------
__global__ __launch_bounds__(256, 2) void k2_gemm1(const float* __restrict__ b1)
{
    extern __shared__ __half sm[];
    __shared__ float s_gsum[128];

    const int tid = threadIdx.x;
    const int n0 = (blockIdx.x & 3) * 128;
    const int m0 = (blockIdx.x >> 2) * 128;
    const int lane = tid & 31, warpId = tid >> 5;
    const int wr = warpId & 3, wc = warpId >> 2;
    const int g = lane >> 2, tig = lane & 3;

    if (tid < 128) s_gsum[tid] = 0.f;

    const __half* Bg = g_w1p + (size_t)n0 * 128;
    float acc[2][8][4] = {};

    const int T = 128 / BK;   // 2
    gemm_issue(sm, 0, tid, m0, 0, g_xnh, 128, Bg, 128);
    gemm_issue(sm, 1, tid, m0, BK, g_xnh, 128, Bg, 128);
    #pragma unroll
    for (int t = 0; t < T; t++) {
        if (t < T - 1) cp_wait1(); else cp_wait0();
        __syncthreads();
        gemm_compute(sm, t, wr, wc, lane, acc);
    }

    // epilogue: bias + exact GELU, store fp16 h, square-sum reduce
    float p[8][2] = {};
    #pragma unroll
    for (int i = 0; i < 2; i++) {
        int r0r = m0 + wr * 32 + i * 16 + g;
        #pragma unroll
        for (int j = 0; j < 8; j++) {
            int cc = n0 + wc * 64 + j * 8 + 2 * tig;
            float b0v = b1[cc], b1v = b1[cc + 1];
            #pragma unroll
            for (int h = 0; h < 2; h++) {
                int rr = r0r + h * 8;
                if (rr < NS) {
                    float v0 = acc[i][j][2 * h + 0] + b0v;
                    float v1 = acc[i][j][2 * h + 1] + b1v;
                    float g0 = 0.5f * v0 * (1.f + erff(v0 * 0.70710678118654752f));
                    float g1 = 0.5f * v1 * (1.f + erff(v1 * 0.70710678118654752f));
                    *(__half2*)(g_hh + (size_t)rr * 512 + cc) = __floats2half2_rn(g0, g1);
                    p[j][0] += g0 * g0;
                    p[j][1] += g1 * g1;
                }
            }
        }
    }
    #pragma unroll
    for (int j = 0; j < 8; j++) {
        #pragma unroll
        for (int c = 0; c < 2; c++) {
            #pragma unroll
            for (int o = 4; o < 32; o <<= 1)
                p[j][c] += __shfl_xor_sync(0xffffffffu, p[j][c], o);
        }
    }
    if (lane < 4) {
        #pragma unroll
        for (int j = 0; j < 8; j++) {
            atomicAdd(&s_gsum[wc * 64 + j * 8 + 2 * lane],     p[j][0]);
            atomicAdd(&s_gsum[wc * 64 + j * 8 + 2 * lane + 1], p[j][1]);
        }
    }
    __syncthreads();
    if (tid < 128) atomicAdd(&g_gsum[n0 + tid], s_gsum[tid]);
}

// ---------------------------------------------------------------------------
// K3: GRN scale
// ---------------------------------------------------------------------------
__global__ void k3_grn(const float* __restrict__ grng)
{
    const int c = threadIdx.x;       // 512 threads
    const int lane = c & 31, warp = c >> 5;
    float gx = sqrtf(g_gsum[c]);

    __shared__ float ws[16];
    __shared__ float s_tot;
    float s = gx;
    #pragma unroll
    for (int o = 16; o > 0; o >>= 1) s += __shfl_xor_sync(0xffffffffu, s, o);
    if (lane == 0) ws[warp] = s;
    __syncthreads();
    if (c == 0) {
        float t = 0.f;
        #pragma unroll
        for (int i = 0; i < 16; i++) t += ws[i];
        s_tot = t;
    }
    __syncthreads();
    float mean = s_tot * (1.f / 512.f);
    g_scale[c] = grng[c] * (gx / (mean + 1e-6f)) + 1.f;
}

// ---------------------------------------------------------------------------
// K3w: fold GRN into transposed B: w2p[n][k] = fp16(scale_k * w2[k][n]);
//      c_n = sum_k grn_b[k] * w2[k][n].  128 blocks (n) x 512 threads (k).
// ---------------------------------------------------------------------------
__global__ __launch_bounds__(512) void k3w_fold(
    const float* __restrict__ w2, const float* __restrict__ grnb)
{
    const int n = blockIdx.x;
    const int k = threadIdx.x;
    const int lane = k & 31, warp = k >> 5;
    float w = w2[(size_t)k * 128 + n];
    g_w2p[(size_t)n * 512 + k] = __float2half_rn(g_scale[k] * w);

    float s = grnb[k] * w;
    __shared__ float ws[16];
    #pragma unroll
    for (int o = 16; o > 0; o >>= 1) s += __shfl_xor_sync(0xffffffffu, s, o);
    if (lane == 0) ws[warp] = s;
    __syncthreads();
    if (k == 0) {
        float t = 0.f;
        #pragma unroll
        for (int i = 0; i < 16; i++) t += ws[i];
        g_c[n] = t;
    }
}

// ---------------------------------------------------------------------------
// K4: GEMM2: out = h @ w2p + (b2 + c) + feats
// ---------------------------------------------------------------------------
__global__ __launch_bounds__(256, 2) void k4_gemm2(
    const float* __restrict__ b2, const float* __restrict__ feats,
    float* __restrict__ out)
{
    extern __shared__ __half sm[];

    const int tid = threadIdx.x;
    const int m0 = blockIdx.x * 128;
    const int lane = tid & 31, warpId = tid >> 5;
    const int wr = warpId & 3, wc = warpId >> 2;
    const int g = lane >> 2, tig = lane & 3;

    float acc[2][8][4] = {};

    const int T = 512 / BK;   // 8
    gemm_issue(sm, 0, tid, m0, 0, g_hh, 512, g_w2p, 512);
    gemm_issue(sm, 1, tid, m0, BK, g_hh, 512, g_w2p, 512);
    #pragma unroll
    for (int t = 0; t < T; t++) {
        if (t < T - 1) cp_wait1(); else cp_wait0();
        __syncthreads();
        if (t + 2 < T)
            gemm_issue(sm, (t + 2) % N_STG, tid, m0, (t + 2) * BK, g_hh, 512, g_w2p, 512);
        gemm_compute(sm, t % N_STG, wr, wc, lane, acc);
    }

    #pragma unroll
    for (int i = 0; i < 2; i++) {
        int r0r = m0 + wr * 32 + i * 16 + g;
        #pragma unroll
        for (int j = 0; j < 8; j++) {
            int cc = wc * 64 + j * 8 + 2 * tig;
            float b0v = b2[cc] + g_c[cc];
            float b1v = b2[cc + 1] + g_c[cc + 1];
            #pragma unroll
            for (int h = 0; h < 2; h++) {
                int rr = r0r + h * 8;
                if (rr < NS) {
                    out[(size_t)rr * 128 + cc] =
                        acc[i][j][2 * h + 0] + b0v + feats[(size_t)rr * 128 + cc];
                    out[(size_t)rr * 128 + cc + 1] =
                        acc[i][j][2 * h + 1] + b1v + feats[(size_t)rr * 128 + cc + 1];
                }
            }
        }
    }
}

// ---------------------------------------------------------------------------
extern "C" void kernel_launch(void* const* d_in, const int* in_sizes, int n_in,
                              void* d_out, int out_size)
{
    const float* feats = (const float*)d_in[0];
    const int*   nidx  = (const int*)  d_in[1];
    const float* dww   = (const float*)d_in[2];
    const float* dwb   = (const float*)d_in[3];
    const float* lng   = (const float*)d_in[4];
    const float* lnb   = (const float*)d_in[5];
    const float* w1    = (const float*)d_in[6];
    const float* b1    = (const float*)d_in[7];
    const float* grng  = (const float*)d_in[8];
    const float* grnb  = (const float*)d_in[9];
    const float* w2    = (const float*)d_in[10];
    const float* b2    = (const float*)d_in[11];
    float* out = (float*)d_out;

    cudaFuncSetAttribute(k2_gemm1, cudaFuncAttributeMaxDynamicSharedMemorySize, SMEM_BYTES);
    cudaFuncSetAttribute(k4_gemm2, cudaFuncAttributeMaxDynamicSharedMemorySize, SMEM_BYTES);

    k0_cvtw1<<<512, 128>>>(w1);
    k0_cvtfeats<<<(NS * D) / 1024, 256>>>(feats);
    k0_cvtdww<<<(KK * D + 1023) / 1024, 256>>>(dww);

    k1_dwln<<<(NS + 7) / 8, 256>>>(nidx, dwb, lng, lnb);

    k2_gemm1<<<((NS + 127) / 128) * 4, 256, SMEM_BYTES>>>(b1);

    k3_grn<<<1, H>>>(grng);
    k3w_fold<<<128, 512>>>(w2, grnb);

    k4_gemm2<<<(NS + 127) / 128, 256, SMEM_BYTES>>>(b2, feats, out);
}

// round 16
// speedup vs baseline: 3.4997x; 1.0197x over previous
#include <cuda_runtime.h>
#include <cuda_fp16.h>
#include <math.h>

#define NS 100000
#define D  128
#define H  512
#define KK 343

// Scratch (device globals; no allocation allowed)
__device__ __half g_fh [(size_t)NS * D];    // feats fp16
__device__ __half g_dwh[(size_t)KK * D];    // dw_w fp16
__device__ __half g_xnh[(size_t)NS * D];    // LN output fp16
__device__ __half g_hh [(size_t)NS * H];    // GELU output fp16
__device__ float  g_gsum[H];
__device__ __half g_w1p[(size_t)H * D];     // w1 transposed [n=512][k=128] fp16
__device__ __half g_w2p[(size_t)D * H];     // scale*w2 transposed [n=128][k=512] fp16
__device__ float  g_c[D];                   // grn_b @ w2 (f32)

__device__ __forceinline__ void mma_f16(float* c, const unsigned* a, const unsigned* b) {
    asm volatile(
        "mma.sync.aligned.m16n8k16.row.col.f32.f16.f16.f32 "
        "{%0,%1,%2,%3}, {%4,%5,%6,%7}, {%8,%9}, {%0,%1,%2,%3};"
        : "+f"(c[0]), "+f"(c[1]), "+f"(c[2]), "+f"(c[3])
        : "r"(a[0]), "r"(a[1]), "r"(a[2]), "r"(a[3]), "r"(b[0]), "r"(b[1]));
}

__device__ __forceinline__ void ldsm4(unsigned* r, const __half* p) {
    unsigned a = (unsigned)__cvta_generic_to_shared(p);
    asm volatile("ldmatrix.sync.aligned.m8n8.x4.shared.b16 {%0,%1,%2,%3}, [%4];"
        : "=r"(r[0]), "=r"(r[1]), "=r"(r[2]), "=r"(r[3]) : "r"(a));
}

__device__ __forceinline__ void cp16(__half* dst, const __half* src) {
    unsigned d = (unsigned)__cvta_generic_to_shared(dst);
    asm volatile("cp.async.cg.shared.global [%0], [%1], 16;" :: "r"(d), "l"(src));
}
__device__ __forceinline__ void cp_commit() { asm volatile("cp.async.commit_group;"); }
__device__ __forceinline__ void cp_wait1()  { asm volatile("cp.async.wait_group 1;"); }
__device__ __forceinline__ void cp_wait0()  { asm volatile("cp.async.wait_group 0;"); }

// Stage geometry: As[128][72] + Bs[128][72] halves (BK=64, pad 8)
#define BK    64
#define LDH   72
#define A_HALFS (128 * LDH)                 // 9216
#define STG_HALFS (2 * A_HALFS)             // 18432 halves
#define N_STG 3
#define SMEM_BYTES (N_STG * STG_HALFS * 2)  // 110592

// ---------------------------------------------------------------------------
// K0: all format conversions in one kernel (grid partitioned).
//  blocks [0, 12500)        : feats -> fp16            (1024 elems/block)
//  blocks [12500, 12564)    : w1 transpose -> g_w1p    (32x32 smem tiles)
//  blocks [12564, 12607)    : dw_w -> fp16
// ---------------------------------------------------------------------------
#define K0_FEATS_BLKS 12500
#define K0_W1_BLKS    64        // (128/32) * (512/32)
#define K0_DW_BLKS    43
#define K0_TOTAL (K0_FEATS_BLKS + K0_W1_BLKS + K0_DW_BLKS)

__global__ __launch_bounds__(256) void k0_convert(
    const float* __restrict__ feats, const float* __restrict__ w1,
    const float* __restrict__ dww)
{
    const int b = blockIdx.x;
    const int tid = threadIdx.x;

    if (b < K0_FEATS_BLKS) {
        size_t i = ((size_t)b * 256 + tid) * 4;
        float4 v = *(const float4*)(feats + i);
        __half2 a = __floats2half2_rn(v.x, v.y);
        __half2 c = __floats2half2_rn(v.z, v.w);
        uint2 p;
        p.x = *(const unsigned*)&a;
        p.y = *(const unsigned*)&c;
        *(uint2*)(g_fh + i) = p;
    } else if (b < K0_FEATS_BLKS + K0_W1_BLKS) {
        // w1 [k=128][n=512] -> g_w1p [n=512][k=128], 32x32 tile transpose
        __shared__ __half tile[32][33];
        int t = b - K0_FEATS_BLKS;           // 0..63
        int kt = (t & 3) * 32;               // k tile base (4 tiles)
        int nt = (t >> 2) * 32;              // n tile base (16 tiles)
        int tx = tid & 31, ty = tid >> 5;    // 32 x 8
        #pragma unroll
        for (int r = 0; r < 4; r++) {
            int k = kt + ty + r * 8;
            tile[ty + r * 8][tx] = __float2half_rn(w1[(size_t)k * 512 + nt + tx]);
        }
        __syncthreads();
        #pragma unroll
        for (int r = 0; r < 4; r++) {
            int n = nt + ty + r * 8;
            g_w1p[(size_t)n * 128 + kt + tx] = tile[tx][ty + r * 8];
        }
    } else {
        int i = ((b - K0_FEATS_BLKS - K0_W1_BLKS) * 256 + tid) * 4;
        if (i < KK * D) {
            float4 v = *(const float4*)(dww + i);
            __half2 a = __floats2half2_rn(v.x, v.y);
            __half2 c = __floats2half2_rn(v.z, v.w);
            uint2 p;
            p.x = *(const unsigned*)&a;
            p.y = *(const unsigned*)&c;
            *(uint2*)(g_dwh + i) = p;
        }
    }
}

// ---------------------------------------------------------------------------
// K1: sparse depthwise conv + LayerNorm. One WARP per site, 4 channels/lane.
// ---------------------------------------------------------------------------
__global__ __launch_bounds__(256) void k1_dwln(
    const int* __restrict__ nidx, const float* __restrict__ dwb,
    const float* __restrict__ lng, const float* __restrict__ lnb)
{
    const int tid  = threadIdx.x;
    const int lane = tid & 31, warp = tid >> 5;
    const int site = blockIdx.x * 8 + warp;

    if (blockIdx.x == 0) {
        if (tid < H) g_gsum[tid] = 0.f;
        if (tid + 256 < H) g_gsum[tid + 256] = 0.f;
    }

    __shared__ int s_list[8][KK];

    const int* row = nidx + (size_t)site * KK;
    int cnt = 0;
    #pragma unroll
    for (int base = 0; base < KK; base += 32) {
        int k  = base + lane;
        int id = (k < KK) ? row[k] : NS;
        bool v = (id != NS);
        unsigned m = __ballot_sync(0xffffffffu, v);
        if (v) s_list[warp][cnt + __popc(m & ((1u << lane) - 1u))] = (k << 17) | id;
        cnt += __popc(m);
    }
    __syncwarp();

    const int c4 = lane * 4;
    float4 acc = make_float4(0.f, 0.f, 0.f, 0.f);
    for (int j = 0; j < cnt; j++) {
        int kid = s_list[warp][j];            // warp-uniform
        int id  = kid & 0x1ffff;
        int k   = kid >> 17;
        uint2 f = *(const uint2*)(g_fh  + (size_t)id * D + c4);
        uint2 w = *(const uint2*)(g_dwh + (size_t)k  * D + c4);
        float2 f0 = __half22float2(*(const __half2*)&f.x);
        float2 f1 = __half22float2(*(const __half2*)&f.y);
        float2 w0 = __half22float2(*(const __half2*)&w.x);
        float2 w1v = __half22float2(*(const __half2*)&w.y);
        acc.x += f0.x * w0.x;  acc.y += f0.y * w0.y;
        acc.z += f1.x * w1v.x; acc.w += f1.y * w1v.y;
    }
    float4 bb = *(const float4*)(dwb + c4);
    float4 x = make_float4(acc.x + bb.x, acc.y + bb.y, acc.z + bb.z, acc.w + bb.w);

    float s  = x.x + x.y + x.z + x.w;
    float s2 = x.x * x.x + x.y * x.y + x.z * x.z + x.w * x.w;
    #pragma unroll
    for (int o = 16; o > 0; o >>= 1) {
        s  += __shfl_xor_sync(0xffffffffu, s,  o);
        s2 += __shfl_xor_sync(0xffffffffu, s2, o);
    }
    float mu  = s  * (1.f / 128.f);
    float var = s2 * (1.f / 128.f) - mu * mu;
    float inv = rsqrtf(var + 1e-6f);

    float4 gg = *(const float4*)(lng + c4);
    float4 be = *(const float4*)(lnb + c4);
    __half2 h01 = __floats2half2_rn((x.x - mu) * inv * gg.x + be.x,
                                    (x.y - mu) * inv * gg.y + be.y);
    __half2 h23 = __floats2half2_rn((x.z - mu) * inv * gg.z + be.z,
                                    (x.w - mu) * inv * gg.w + be.w);
    uint2 packed;
    packed.x = *(const unsigned*)&h01;
    packed.y = *(const unsigned*)&h23;
    *(uint2*)(g_xnh + (size_t)site * D + c4) = packed;
}

// ---------------------------------------------------------------------------
// GEMM mainloop (BM=128, BN=128, BK=64, fp16 m16n8k16, 8 warps 4x2, 32x64
// warp tile, ldmatrix fragment loads). B stored transposed [n][k] in gmem.
// ---------------------------------------------------------------------------
__device__ __forceinline__ void gemm_issue(
    __half* sm, int st, int tid, int m0, int k0,
    const __half* __restrict__ Ag, int lda,
    const __half* __restrict__ Bg, int ldb)
{
    __half* As = sm + st * STG_HALFS;
    __half* Bs = As + A_HALFS;
    #pragma unroll
    for (int j = 0; j < 4; j++) {
        int idx = tid + j * 256;
        int r = idx >> 3, q = idx & 7;
        int gr = m0 + r;
        if (gr < NS) cp16(&As[r * LDH + q * 8], Ag + (size_t)gr * lda + k0 + q * 8);
    }
    #pragma unroll
    for (int j = 0; j < 4; j++) {
        int idx = tid + j * 256;
        int nr = idx >> 3, q = idx & 7;
        cp16(&Bs[nr * LDH + q * 8], Bg + (size_t)nr * ldb + k0 + q * 8);
    }
    cp_commit();
}

__device__ __forceinline__ void gemm_compute(
    const __half* sm, int st, int wr, int wc, int lane,
    float acc[2][8][4])
{
    const __half* As = sm + st * STG_HALFS;
    const __half* Bs = As + A_HALFS;
    #pragma unroll
    for (int kb = 0; kb < BK; kb += 16) {
        unsigned bfr[8][2];
        #pragma unroll
        for (int jj = 0; jj < 4; jj++) {
            int n = wc * 64 + jj * 16 + (lane & 7) + ((lane >> 4) << 3);
            int c = kb + (((lane >> 3) & 1) << 3);
            unsigned t[4];
            ldsm4(t, &Bs[n * LDH + c]);
            bfr[2 * jj][0] = t[0]; bfr[2 * jj][1] = t[1];
            bfr[2 * jj + 1][0] = t[2]; bfr[2 * jj + 1][1] = t[3];
        }
        #pragma unroll
        for (int i = 0; i < 2; i++) {
            int r = wr * 32 + i * 16 + (lane & 15);
            int c = kb + ((lane >> 4) << 3);
            unsigned afr[4];
            ldsm4(afr, &As[r * LDH + c]);
            #pragma unroll
            for (int j = 0; j < 8; j++) mma_f16(acc[i][j], afr, bfr[j]);
        }
    }
}

// ---------------------------------------------------------------------------
// K2: GEMM1: h = gelu(xn @ w1 + b1); stores fp16 h + per-channel sum h^2
// ---------------------------------------------------------------------------
__global__ __launch_bounds__(256, 2) void k2_gemm1(const float* __restrict__ b1)
{
    extern __shared__ __half sm[];
    __shared__ float s_gsum[128];

    const int tid = threadIdx.x;
    const int n0 = (blockIdx.x & 3) * 128;
    const int m0 = (blockIdx.x >> 2) * 128;
    const int lane = tid & 31, warpId = tid >> 5;
    const int wr = warpId & 3, wc = warpId >> 2;
    const int g = lane >> 2, tig = lane & 3;

    if (tid < 128) s_gsum[tid] = 0.f;

    const __half* Bg = g_w1p + (size_t)n0 * 128;
    float acc[2][8][4] = {};

    const int T = 128 / BK;   // 2
    gemm_issue(sm, 0, tid, m0, 0, g_xnh, 128, Bg, 128);
    gemm_issue(sm, 1, tid, m0, BK, g_xnh, 128, Bg, 128);
    #pragma unroll
    for (int t = 0; t < T; t++) {
        if (t < T - 1) cp_wait1(); else cp_wait0();
        __syncthreads();
        gemm_compute(sm, t, wr, wc, lane, acc);
    }

    // epilogue: bias + exact GELU, store fp16 h, square-sum reduce
    float p[8][2] = {};
    #pragma unroll
    for (int i = 0; i < 2; i++) {
        int r0r = m0 + wr * 32 + i * 16 + g;
        #pragma unroll
        for (int j = 0; j < 8; j++) {
            int cc = n0 + wc * 64 + j * 8 + 2 * tig;
            float b0v = b1[cc], b1v = b1[cc + 1];
            #pragma unroll
            for (int h = 0; h < 2; h++) {
                int rr = r0r + h * 8;
                if (rr < NS) {
                    float v0 = acc[i][j][2 * h + 0] + b0v;
                    float v1 = acc[i][j][2 * h + 1] + b1v;
                    float g0 = 0.5f * v0 * (1.f + erff(v0 * 0.70710678118654752f));
                    float g1 = 0.5f * v1 * (1.f + erff(v1 * 0.70710678118654752f));
                    *(__half2*)(g_hh + (size_t)rr * 512 + cc) = __floats2half2_rn(g0, g1);
                    p[j][0] += g0 * g0;
                    p[j][1] += g1 * g1;
                }
            }
        }
    }
    #pragma unroll
    for (int j = 0; j < 8; j++) {
        #pragma unroll
        for (int c = 0; c < 2; c++) {
            #pragma unroll
            for (int o = 4; o < 32; o <<= 1)
                p[j][c] += __shfl_xor_sync(0xffffffffu, p[j][c], o);
        }
    }
    if (lane < 4) {
        #pragma unroll
        for (int j = 0; j < 8; j++) {
            atomicAdd(&s_gsum[wc * 64 + j * 8 + 2 * lane],     p[j][0]);
            atomicAdd(&s_gsum[wc * 64 + j * 8 + 2 * lane + 1], p[j][1]);
        }
    }
    __syncthreads();
    if (tid < 128) atomicAdd(&g_gsum[n0 + tid], s_gsum[tid]);
}

// ---------------------------------------------------------------------------
// K3: fused GRN scale + fold into transposed B of GEMM2.
// Each of 128 blocks (n) redundantly recomputes the GRN scale from g_gsum
// (deterministic), then writes w2p[n][k] = fp16(scale_k*w2[k][n]) and
// c_n = sum_k grn_b[k]*w2[k][n].
// ---------------------------------------------------------------------------
__global__ __launch_bounds__(512) void k3_fold(
    const float* __restrict__ w2, const float* __restrict__ grnb,
    const float* __restrict__ grng)
{
    const int n = blockIdx.x;
    const int k = threadIdx.x;
    const int lane = k & 31, warp = k >> 5;

    __shared__ float ws[16];
    __shared__ float s_tot;

    // recompute GRN scale for channel k
    float gx = sqrtf(g_gsum[k]);
    float s = gx;
    #pragma unroll
    for (int o = 16; o > 0; o >>= 1) s += __shfl_xor_sync(0xffffffffu, s, o);
    if (lane == 0) ws[warp] = s;
    __syncthreads();
    if (k == 0) {
        float t = 0.f;
        #pragma unroll
        for (int i = 0; i < 16; i++) t += ws[i];
        s_tot = t;
    }
    __syncthreads();
    float mean = s_tot * (1.f / 512.f);
    float scale = grng[k] * (gx / (mean + 1e-6f)) + 1.f;

    float w = w2[(size_t)k * 128 + n];
    g_w2p[(size_t)n * 512 + k] = __float2half_rn(scale * w);

    // c_n = sum_k grn_b[k] * w2[k][n]
    __syncthreads();
    float cs = grnb[k] * w;
    #pragma unroll
    for (int o = 16; o > 0; o >>= 1) cs += __shfl_xor_sync(0xffffffffu, cs, o);
    if (lane == 0) ws[warp] = cs;
    __syncthreads();
    if (k == 0) {
        float t = 0.f;
        #pragma unroll
        for (int i = 0; i < 16; i++) t += ws[i];
        g_c[n] = t;
    }
}

// ---------------------------------------------------------------------------
// K4: GEMM2: out = h @ w2p + (b2 + c) + feats
// ---------------------------------------------------------------------------
__global__ __launch_bounds__(256, 2) void k4_gemm2(
    const float* __restrict__ b2, const float* __restrict__ feats,
    float* __restrict__ out)
{
    extern __shared__ __half sm[];

    const int tid = threadIdx.x;
    const int m0 = blockIdx.x * 128;
    const int lane = tid & 31, warpId = tid >> 5;
    const int wr = warpId & 3, wc = warpId >> 2;
    const int g = lane >> 2, tig = lane & 3;

    float acc[2][8][4] = {};

    const int T = 512 / BK;   // 8
    gemm_issue(sm, 0, tid, m0, 0, g_hh, 512, g_w2p, 512);
    gemm_issue(sm, 1, tid, m0, BK, g_hh, 512, g_w2p, 512);
    #pragma unroll
    for (int t = 0; t < T; t++) {
        if (t < T - 1) cp_wait1(); else cp_wait0();
        __syncthreads();
        if (t + 2 < T)
            gemm_issue(sm, (t + 2) % N_STG, tid, m0, (t + 2) * BK, g_hh, 512, g_w2p, 512);
        gemm_compute(sm, t % N_STG, wr, wc, lane, acc);
    }

    #pragma unroll
    for (int i = 0; i < 2; i++) {
        int r0r = m0 + wr * 32 + i * 16 + g;
        #pragma unroll
        for (int j = 0; j < 8; j++) {
            int cc = wc * 64 + j * 8 + 2 * tig;
            float b0v = b2[cc] + g_c[cc];
            float b1v = b2[cc + 1] + g_c[cc + 1];
            #pragma unroll
            for (int h = 0; h < 2; h++) {
                int rr = r0r + h * 8;
                if (rr < NS) {
                    out[(size_t)rr * 128 + cc] =
                        acc[i][j][2 * h + 0] + b0v + feats[(size_t)rr * 128 + cc];
                    out[(size_t)rr * 128 + cc + 1] =
                        acc[i][j][2 * h + 1] + b1v + feats[(size_t)rr * 128 + cc + 1];
                }
            }
        }
    }
}

// ---------------------------------------------------------------------------
extern "C" void kernel_launch(void* const* d_in, const int* in_sizes, int n_in,
                              void* d_out, int out_size)
{
    const float* feats = (const float*)d_in[0];
    const int*   nidx  = (const int*)  d_in[1];
    const float* dww   = (const float*)d_in[2];
    const float* dwb   = (const float*)d_in[3];
    const float* lng   = (const float*)d_in[4];
    const float* lnb   = (const float*)d_in[5];
    const float* w1    = (const float*)d_in[6];
    const float* b1    = (const float*)d_in[7];
    const float* grng  = (const float*)d_in[8];
    const float* grnb  = (const float*)d_in[9];
    const float* w2    = (const float*)d_in[10];
    const float* b2    = (const float*)d_in[11];
    float* out = (float*)d_out;

    cudaFuncSetAttribute(k2_gemm1, cudaFuncAttributeMaxDynamicSharedMemorySize, SMEM_BYTES);
    cudaFuncSetAttribute(k4_gemm2, cudaFuncAttributeMaxDynamicSharedMemorySize, SMEM_BYTES);

    k0_convert<<<K0_TOTAL, 256>>>(feats, w1, dww);

    k1_dwln<<<(NS + 7) / 8, 256>>>(nidx, dwb, lng, lnb);

    k2_gemm1<<<((NS + 127) / 128) * 4, 256, SMEM_BYTES>>>(b1);

    k3_fold<<<128, 512>>>(w2, grnb, grng);

    k4_gemm2<<<(NS + 127) / 128, 256, SMEM_BYTES>>>(b2, feats, out);
}